// round 7
// baseline (speedup 1.0000x reference)
#include <cuda_runtime.h>

#define T49   49
#define TPAD  56
#define CDIM  128
#define NH    4
#define HDIM  32
#define NWIN  64

#define XP    132          // x_s / out2 pitch (floats)
#define QP    390          // qkv pitch (floats)
#define WSP   129          // staged-W pitch (float2 units)
#define AP    56           // attn pitch (floats)

#define OFF_X    0
#define OFF_W    (TPAD*XP)                 /* 7392  : W stage | attn     */
#define OFF_QKV  (OFF_W + 2*64*WSP)        /* 23904 : qkv               */
#define SMEM_FLOATS (OFF_QKV + TPAD*QP)    /* 45744                     */
#define SMEM_BYTES  (SMEM_FLOATS*4)        /* 182976                    */

typedef unsigned long long u64;

// packed fp32x2 FMA (Blackwell): d.lo += a.lo*b.lo ; d.hi += a.hi*b.hi
__device__ __forceinline__ void ffma2(u64 &d, u64 a, u64 b){
  asm("fma.rn.f32x2 %0, %1, %2, %0;" : "+l"(d) : "l"(a), "l"(b));
}
__device__ __forceinline__ u64 splat2(float x){
  u64 r; asm("mov.b64 %0, {%1, %1};" : "=l"(r) : "f"(x)); return r;
}
__device__ __forceinline__ float lohi(u64 v){
  float lo, hi; asm("mov.b64 {%0, %1}, %2;" : "=f"(lo), "=f"(hi) : "l"(v));
  return lo + hi;
}
__device__ __forceinline__ u64 lds64(const float* p){
  return *reinterpret_cast<const u64*>(p);
}

__global__ void __launch_bounds__(512, 1)
wattn_kernel(const float* __restrict__ x, const float* __restrict__ mask,
             const float* __restrict__ qkv_w, const float* __restrict__ qkv_b,
             const float* __restrict__ proj_w, const float* __restrict__ proj_b,
             const float* __restrict__ bias_table, float* __restrict__ out)
{
  extern __shared__ float sm[];
  float*  x_s  = sm + OFF_X;    // stage 1/2
  float*  o2   = sm + OFF_X;    // reuse: attn@V result (stage 3b/4)
  float*  w_s  = sm + OFF_W;    // staged weights (stage 2/4)
  float*  attn = sm + OFF_W;    // reuse: attention logits (stage 3)
  float*  qkv  = sm + OFF_QKV;
  float2* wk2  = reinterpret_cast<float2*>(w_s);

  const int b   = blockIdx.x;
  const int tid = threadIdx.x;
  const int tx  = tid & 31;          // lane
  const int w   = tid >> 5;          // warp 0..15
  const int r0  = (w & 7) * 7;       // 7-row group
  const int cg  = w >> 3;            // column-group (stages 2/4, 3b)

  // ---------------- stage 1: load x tile (49x128, pad rows to 56 with 0) ----
  {
    const float4* xg = reinterpret_cast<const float4*>(x + (size_t)b*(T49*CDIM));
    #pragma unroll
    for (int it = 0; it < 4; ++it) {
      int i4 = tid + it*512;
      if (i4 < T49*CDIM/4) {
        float4 v = __ldg(xg + i4);
        *reinterpret_cast<float4*>(&x_s[(i4 >> 5)*XP + (i4 & 31)*4]) = v;
      }
    }
    if (tid < (TPAD-T49)*32) {
      *reinterpret_cast<float4*>(&x_s[(T49 + (tid >> 5))*XP + (tid & 31)*4]) =
          make_float4(0.f, 0.f, 0.f, 0.f);
    }
  }
  __syncthreads();

  // ------------- stage 2: QKV = x @ qkv_w^T + qkv_b, 3 chunks, col-split ----
  for (int ch = 0; ch < 3; ++ch) {
    const float* wg = qkv_w + ch*CDIM*CDIM;
    #pragma unroll
    for (int it = 0; it < 16; ++it) {      // stage W chunk as k-pair-major
      int i  = tid + it*512;
      int c  = i >> 6, k2 = i & 63;
      wk2[k2*WSP + c] = __ldg(reinterpret_cast<const float2*>(wg + c*CDIM) + k2);
    }
    __syncthreads();

    u64 acc[7][2];
    #pragma unroll
    for (int i = 0; i < 7; ++i) { acc[i][0] = 0ull; acc[i][1] = 0ull; }

    const int c0 = cg*64 + tx;             // this warp's 2 column strips
    #pragma unroll 2
    for (int e = 0; e < 32; ++e) {         // 2 k-pairs per iter
      int k2a = 2*e;
      u64 b0[2], b1[2];
      #pragma unroll
      for (int j = 0; j < 2; ++j) {        // lane-consecutive, conflict-free
        b0[j] = lds64(reinterpret_cast<const float*>(&wk2[ k2a   *WSP + c0 + 32*j]));
        b1[j] = lds64(reinterpret_cast<const float*>(&wk2[(k2a+1)*WSP + c0 + 32*j]));
      }
      #pragma unroll
      for (int i = 0; i < 7; ++i) {        // uniform-address 16B load
        ulonglong2 av = *reinterpret_cast<const ulonglong2*>(&x_s[(r0+i)*XP + 2*k2a]);
        #pragma unroll
        for (int j = 0; j < 2; ++j) {
          ffma2(acc[i][j], av.x, b0[j]);
          ffma2(acc[i][j], av.y, b1[j]);
        }
      }
    }

    #pragma unroll
    for (int i = 0; i < 7; ++i) {
      int r = r0 + i;
      #pragma unroll
      for (int j = 0; j < 2; ++j) {
        int cc = ch*CDIM + c0 + 32*j;
        qkv[r*QP + cc] = (r < T49) ? (lohi(acc[i][j]) + __ldg(&qkv_b[cc])) : 0.f;
      }
    }
    __syncthreads();
  }

  // -------- stage 3a: attn = scale*q.k + bias + mask (2 units per warp) -----
  {
    const float scale = 0.17677669529663687f;   // 32^-0.5
    const float* mrow = mask + (size_t)(b & (NWIN-1))*(T49*T49);
    const int s1 = (tx + 32 < TPAD) ? (tx + 32) : 0;   // clamp (store guarded)
    #pragma unroll 1
    for (int u = 0; u < 2; ++u) {
      const int uid = w*2 + u;              // 32 units = 4 heads x 8 row-groups
      const int h   = uid >> 3;
      const int rr0 = (uid & 7) * 7;
      const int qo = h*HDIM, ko = CDIM + h*HDIM;

      u64 acc[7][2];
      #pragma unroll
      for (int i = 0; i < 7; ++i) { acc[i][0] = 0ull; acc[i][1] = 0ull; }
      #pragma unroll 4
      for (int d2 = 0; d2 < 16; ++d2) {
        u64 b0 = lds64(&qkv[tx*QP + ko + 2*d2]);
        u64 b1 = lds64(&qkv[s1*QP + ko + 2*d2]);
        #pragma unroll
        for (int i = 0; i < 7; ++i) {
          u64 aa = lds64(&qkv[(rr0+i)*QP + qo + 2*d2]);
          ffma2(acc[i][0], aa, b0);
          ffma2(acc[i][1], aa, b1);
        }
      }
      #pragma unroll
      for (int i = 0; i < 7; ++i) {
        int t = rr0 + i;
        int th = t / 7, tw = t - th*7;
        #pragma unroll
        for (int j = 0; j < 2; ++j) {
          int s = tx + 32*j;
          if (s < TPAD) {
            float v = lohi(acc[i][j]) * scale;
            if (t < T49 && s < T49) {
              int sh  = s / 7, sw = s - sh*7;
              int rel = (th - sh + 6)*13 + (tw - sw + 6);
              v += __ldg(&bias_table[rel*NH + h]) + __ldg(&mrow[t*T49 + s]);
            }
            attn[(h*TPAD + t)*AP + s] = v;
          }
        }
      }
    }
  }
  __syncthreads();

  // ---------------- stage 3b: out2 = attn @ v (row x col split) -------------
  {
    const int cp = cg*32 + tx;               // column pair: c = 2*cp, cp in [0,64)
    const int h0 = cp >> 4;                  // head = cp/16
    u64 acc[7];
    #pragma unroll
    for (int i = 0; i < 7; ++i) acc[i] = 0ull;
    #pragma unroll 4
    for (int s = 0; s < TPAD; ++s) {         // v rows >=49 are zero: safe
      u64 b0 = lds64(&qkv[s*QP + 2*CDIM + 2*cp]);
      #pragma unroll
      for (int i = 0; i < 7; ++i)
        ffma2(acc[i], splat2(attn[(h0*TPAD + r0 + i)*AP + s]), b0);
    }
    #pragma unroll
    for (int i = 0; i < 7; ++i)              // o2 region (x_s) long dead
      *reinterpret_cast<u64*>(&o2[(r0+i)*XP + 2*cp]) = acc[i];
  }
  __syncthreads();

  // ------------- stage 4: out = o2 @ proj_w^T + proj_b (col-split) ---------
  {
    #pragma unroll
    for (int it = 0; it < 16; ++it) {        // attn region free now
      int i  = tid + it*512;
      int c  = i >> 6, k2 = i & 63;
      wk2[k2*WSP + c] = __ldg(reinterpret_cast<const float2*>(proj_w + c*CDIM) + k2);
    }
    __syncthreads();

    u64 acc[7][2];
    #pragma unroll
    for (int i = 0; i < 7; ++i) { acc[i][0] = 0ull; acc[i][1] = 0ull; }

    const int c0 = cg*64 + tx;
    #pragma unroll 2
    for (int e = 0; e < 32; ++e) {
      int k2a = 2*e;
      u64 b0[2], b1[2];
      #pragma unroll
      for (int j = 0; j < 2; ++j) {
        b0[j] = lds64(reinterpret_cast<const float*>(&wk2[ k2a   *WSP + c0 + 32*j]));
        b1[j] = lds64(reinterpret_cast<const float*>(&wk2[(k2a+1)*WSP + c0 + 32*j]));
      }
      #pragma unroll
      for (int i = 0; i < 7; ++i) {
        ulonglong2 av = *reinterpret_cast<const ulonglong2*>(&o2[(r0+i)*XP + 2*k2a]);
        #pragma unroll
        for (int j = 0; j < 2; ++j) {
          ffma2(acc[i][j], av.x, b0[j]);
          ffma2(acc[i][j], av.y, b1[j]);
        }
      }
    }

    float* og = out + (size_t)b*(T49*CDIM);
    #pragma unroll
    for (int i = 0; i < 7; ++i) {
      int r = r0 + i;
      if (r < T49) {
        #pragma unroll
        for (int j = 0; j < 2; ++j) {
          int c = c0 + 32*j;                 // lane-consecutive: coalesced
          og[r*CDIM + c] = lohi(acc[i][j]) + __ldg(&proj_b[c]);
        }
      }
    }
  }
}

extern "C" void kernel_launch(void* const* d_in, const int* in_sizes, int n_in,
                              void* d_out, int out_size)
{
  const float* x      = (const float*)d_in[0];
  const float* mask   = (const float*)d_in[1];
  const float* qkv_w  = (const float*)d_in[2];
  const float* qkv_b  = (const float*)d_in[3];
  const float* proj_w = (const float*)d_in[4];
  const float* proj_b = (const float*)d_in[5];
  const float* btab   = (const float*)d_in[6];
  float* out = (float*)d_out;

  int B = in_sizes[0] / (T49*CDIM);   // 8192 windows

  cudaFuncSetAttribute(wattn_kernel,
                       cudaFuncAttributeMaxDynamicSharedMemorySize, SMEM_BYTES);
  wattn_kernel<<<B, 512, SMEM_BYTES>>>(x, mask, qkv_w, qkv_b,
                                       proj_w, proj_b, btab, out);
}

// round 9
// speedup vs baseline: 1.4778x; 1.4778x over previous
#include <cuda_runtime.h>
#include <cuda_bf16.h>

typedef unsigned long long u64;
typedef unsigned int u32;

#define T49   49
#define TPAD  56
#define CDIM  128
#define NH    4
#define HDIM  32
#define QP    390
#define AP    56
#define OP    132
#define TP    136                     /* bf16 tile pitch (bf16 units, 272B/row) */

#define QKV_OFF  0                    /* fp32 qkv 56x390x4 = 87360 ; o_s alias  */
#define XH_OFF   87360                /* A tile 64x136 bf16 hi (17408B)         */
#define XL_OFF   (XH_OFF+17408)
#define WH_OFF   (XL_OFF+17408)       /* W tile 128x136 bf16 hi (34816B); attn alias */
#define WL_OFF   (WH_OFF+34816)
#define ATTN_OFF WH_OFF
#define SMEM_BYTES (WL_OFF+34816)     /* 191808 */

// ---------------- helpers --------------------------------------------------
__device__ __forceinline__ u32 smem_u32(const void* p){
  u32 a; asm("{ .reg .u64 t; cvta.to.shared.u64 t, %1; cvt.u32.u64 %0, t; }"
             : "=r"(a) : "l"(p));
  return a;
}
__device__ __forceinline__ void ffma2(u64 &d, u64 a, u64 b){
  asm("fma.rn.f32x2 %0, %1, %2, %0;" : "+l"(d) : "l"(a), "l"(b));
}
__device__ __forceinline__ u64 splat2(float x){
  u64 r; asm("mov.b64 %0, {%1, %1};" : "=l"(r) : "f"(x)); return r;
}
__device__ __forceinline__ float lohi(u64 v){
  float lo, hi; asm("mov.b64 {%0, %1}, %2;" : "=f"(lo), "=f"(hi) : "l"(v));
  return lo + hi;
}
__device__ __forceinline__ void unpk2(u64 v, float &lo, float &hi){
  asm("mov.b64 {%0, %1}, %2;" : "=f"(lo), "=f"(hi) : "l"(v));
}
__device__ __forceinline__ u64 lds64(const float* p){
  return *reinterpret_cast<const u64*>(p);
}
__device__ __forceinline__ u32 pkbf(float a, float b){
  __nv_bfloat16 x=__float2bfloat16_rn(a), y=__float2bfloat16_rn(b);
  return (u32)__bfloat16_as_ushort(x) | ((u32)__bfloat16_as_ushort(y)<<16);
}
// split fp32x4 -> bf16 hi + bf16 residual, 8B store each (byte offset)
__device__ __forceinline__ void split_store4(char* th, char* tl, u32 off, float4 v){
  __nv_bfloat16 h0=__float2bfloat16_rn(v.x), h1=__float2bfloat16_rn(v.y);
  __nv_bfloat16 h2=__float2bfloat16_rn(v.z), h3=__float2bfloat16_rn(v.w);
  u64 hw = (u64)((u32)__bfloat16_as_ushort(h0)|((u32)__bfloat16_as_ushort(h1)<<16))
         | ((u64)((u32)__bfloat16_as_ushort(h2)|((u32)__bfloat16_as_ushort(h3)<<16))<<32);
  u64 lw = (u64)pkbf(v.x-__bfloat162float(h0), v.y-__bfloat162float(h1))
         | ((u64)pkbf(v.z-__bfloat162float(h2), v.w-__bfloat162float(h3))<<32);
  *reinterpret_cast<u64*>(th+off) = hw;
  *reinterpret_cast<u64*>(tl+off) = lw;
}
// stage a 128x128 fp32 weight block (row = out-channel n, col = k) into tiles
__device__ __forceinline__ void stage_w(char* dh, char* dl, const float* wg, int tid){
  #pragma unroll
  for (int it = 0; it < 16; ++it){
    int e4 = tid + it*256;
    int n = e4>>5, k4 = (e4&31)*4;
    float4 v = __ldg(reinterpret_cast<const float4*>(wg + n*CDIM) + (e4&31));
    split_store4(dh, dl, (u32)(n*TP + k4)*2, v);
  }
}
// ---------------- mma.sync / ldmatrix (base sm_80+ PTX) -------------------
__device__ __forceinline__ void ldmA(u32* r, u32 addr){
  asm volatile("ldmatrix.sync.aligned.m8n8.x4.shared.b16 {%0,%1,%2,%3}, [%4];"
    : "=r"(r[0]),"=r"(r[1]),"=r"(r[2]),"=r"(r[3]) : "r"(addr));
}
__device__ __forceinline__ void ldmB(u32* r, u32 addr){
  asm volatile("ldmatrix.sync.aligned.m8n8.x2.shared.b16 {%0,%1}, [%2];"
    : "=r"(r[0]),"=r"(r[1]) : "r"(addr));
}
__device__ __forceinline__ void mma16816(float* c, const u32* a, const u32* b){
  asm volatile("mma.sync.aligned.m16n8k16.row.col.f32.bf16.bf16.f32 "
    "{%0,%1,%2,%3}, {%4,%5,%6,%7}, {%8,%9}, {%0,%1,%2,%3};"
    : "+f"(c[0]),"+f"(c[1]),"+f"(c[2]),"+f"(c[3])
    : "r"(a[0]),"r"(a[1]),"r"(a[2]),"r"(a[3]), "r"(b[0]),"r"(b[1]));
}
// 64x128x128 GEMM, 3-term split bf16; warp (wm,wn) owns 32x32 of output
__device__ __forceinline__ void mma_gemm(
    u32 aH, u32 aL, u32 bH, u32 bL,
    int wm, int wn, int lr, int lk, int br, int bk, float acc[2][4][4])
{
  #pragma unroll
  for (int k0 = 0; k0 < 128; k0 += 16){
    u32 ah[2][4], al[2][4], bh[4][2], bl[4][2];
    #pragma unroll
    for (int mt = 0; mt < 2; ++mt){
      u32 ar = (u32)((wm*32 + mt*16 + lr)*TP + k0 + lk*8)*2;
      ldmA(ah[mt], aH + ar);
      ldmA(al[mt], aL + ar);
    }
    #pragma unroll
    for (int nt = 0; nt < 4; ++nt){
      u32 brr = (u32)((wn*32 + nt*8 + br)*TP + k0 + bk*8)*2;
      ldmB(bh[nt], bH + brr);
      ldmB(bl[nt], bL + brr);
    }
    #pragma unroll
    for (int mt = 0; mt < 2; ++mt)
      #pragma unroll
      for (int nt = 0; nt < 4; ++nt){
        mma16816(acc[mt][nt], ah[mt], bh[nt]);
        mma16816(acc[mt][nt], ah[mt], bl[nt]);
        mma16816(acc[mt][nt], al[mt], bh[nt]);
      }
  }
}

__global__ void __launch_bounds__(256, 1)
wattn_kernel(const float* __restrict__ x, const float* __restrict__ mask,
             const float* __restrict__ qkv_w, const float* __restrict__ qkv_b,
             const float* __restrict__ proj_w, const float* __restrict__ proj_b,
             const float* __restrict__ bias_table, float* __restrict__ out)
{
  extern __shared__ char smc[];
  float* qkv  = reinterpret_cast<float*>(smc + QKV_OFF);
  float* o_s  = reinterpret_cast<float*>(smc + QKV_OFF);    // alias
  float* attn = reinterpret_cast<float*>(smc + ATTN_OFF);   // alias over W tiles
  char*  xh = smc + XH_OFF;  char* xl = smc + XL_OFF;
  char*  wh = smc + WH_OFF;  char* wl = smc + WL_OFF;

  const u32 sm0 = smem_u32(smc);
  const u32 aHs = sm0 + XH_OFF, aLs = sm0 + XL_OFF;
  const u32 bHs = sm0 + WH_OFF, bLs = sm0 + WL_OFF;

  const int b   = blockIdx.x;
  const int tid = threadIdx.x;
  const int tx  = tid & 31;
  const int w   = tid >> 5;                 // warp 0..7
  const int lr = tx & 15, lk = tx >> 4;     // A ldmatrix lane roles
  const int br = tx & 7,  bk = (tx >> 3) & 1;
  const int quad = tx >> 2, qc = tx & 3;    // D fragment lane roles
  const int wm = w & 1, wn = w >> 1;        // 2 x 4 warp grid over 64x128

  // ---- stage 1: x -> bf16 hi/lo A tiles (rows 49..63 zeroed) --------------
  {
    const float4* xg = reinterpret_cast<const float4*>(x + (size_t)b*(T49*CDIM));
    #pragma unroll
    for (int it = 0; it < 7; ++it) {
      int e4 = tid + it*256;
      if (e4 < T49*32) {
        int r = e4 >> 5, c4 = (e4 & 31)*4;
        split_store4(xh, xl, (u32)(r*TP + c4)*2, __ldg(xg + e4));
      }
    }
    #pragma unroll
    for (int i2 = 0; i2 < 2; ++i2) {
      int i = tid + i2*256;
      if (i < 15*34) {
        int r = 49 + i/34, c8 = i%34;
        *reinterpret_cast<u64*>(xh + (u32)(r*TP)*2 + c8*8) = 0ull;
        *reinterpret_cast<u64*>(xl + (u32)(r*TP)*2 + c8*8) = 0ull;
      }
    }
    stage_w(wh, wl, qkv_w, tid);
  }
  __syncthreads();

  // ---- stage 2: QKV = x @ Wqkv^T + b, 3 chunks of N=128 via HMMA ----------
  #pragma unroll 1
  for (int ch = 0; ch < 3; ++ch) {
    float acc[2][4][4];
    #pragma unroll
    for (int mt=0;mt<2;++mt)
      #pragma unroll
      for (int nt=0;nt<4;++nt)
        #pragma unroll
        for (int e=0;e<4;++e) acc[mt][nt][e] = 0.f;

    mma_gemm(aHs, aLs, bHs, bLs, wm, wn, lr, lk, br, bk, acc);

    #pragma unroll
    for (int mt = 0; mt < 2; ++mt)
      #pragma unroll
      for (int nt = 0; nt < 4; ++nt) {
        int c  = ch*CDIM + wn*32 + nt*8 + qc*2;
        float2 bb = __ldg(reinterpret_cast<const float2*>(qkv_b + c));
        int r1 = wm*32 + mt*16 + quad, r2 = r1 + 8;
        if (r1 < T49)
          *reinterpret_cast<float2*>(&qkv[r1*QP + c]) =
              make_float2(acc[mt][nt][0]+bb.x, acc[mt][nt][1]+bb.y);
        else if (r1 < TPAD)
          *reinterpret_cast<float2*>(&qkv[r1*QP + c]) = make_float2(0.f,0.f);
        if (r2 < T49)
          *reinterpret_cast<float2*>(&qkv[r2*QP + c]) =
              make_float2(acc[mt][nt][2]+bb.x, acc[mt][nt][3]+bb.y);
        else if (r2 < TPAD)
          *reinterpret_cast<float2*>(&qkv[r2*QP + c]) = make_float2(0.f,0.f);
      }
    __syncthreads();
    if (ch < 2) {
      stage_w(wh, wl, qkv_w + (ch+1)*CDIM*CDIM, tid);
      __syncthreads();
    }
  }

  // ---- stage 3a: attn = scale*q.k + bias + mask (FFMA, 8 warps) -----------
  {
    const float scale = 0.17677669529663687f;   // 32^-0.5
    const float* mrow = mask + (size_t)(b & 63)*(T49*T49);
    const int s1 = (tx + 32 < TPAD) ? (tx + 32) : 0;
    const int r0 = w*7;
    #pragma unroll 1
    for (int h = 0; h < NH; ++h) {
      const int qo = h*HDIM, ko = CDIM + h*HDIM;
      u64 acc[7][2];
      #pragma unroll
      for (int i = 0; i < 7; ++i) { acc[i][0] = 0ull; acc[i][1] = 0ull; }
      #pragma unroll 4
      for (int d2 = 0; d2 < 16; ++d2) {
        u64 b0 = lds64(&qkv[tx*QP + ko + 2*d2]);
        u64 b1 = lds64(&qkv[s1*QP + ko + 2*d2]);
        #pragma unroll
        for (int i = 0; i < 7; ++i) {
          u64 aa = lds64(&qkv[(r0+i)*QP + qo + 2*d2]);
          ffma2(acc[i][0], aa, b0);
          ffma2(acc[i][1], aa, b1);
        }
      }
      #pragma unroll
      for (int i = 0; i < 7; ++i) {
        int t = r0 + i;
        int th = t / 7, tw = t - th*7;
        #pragma unroll
        for (int j = 0; j < 2; ++j) {
          int s = tx + 32*j;
          if (s < TPAD) {
            float v = lohi(acc[i][j]) * scale;
            if (t < T49 && s < T49) {
              int sh  = s / 7, sw = s - sh*7;
              int rel = (th - sh + 6)*13 + (tw - sw + 6);
              v += __ldg(&bias_table[rel*NH + h]) + __ldg(&mrow[t*T49 + s]);
            }
            attn[(h*TPAD + t)*AP + s] = v;
          }
        }
      }
    }
  }
  __syncthreads();

  // ---- stage 3b: o2 = attn @ v, split-bf16 straight into A tiles ----------
  {
    const int r0 = w*7;
    const int cp0 = tx, cp1 = tx + 32;       // col pairs: c = 2*cp
    const int h0 = cp0 >> 4, h1 = cp1 >> 4;
    u64 acc[7][2];
    #pragma unroll
    for (int i = 0; i < 7; ++i) { acc[i][0] = 0ull; acc[i][1] = 0ull; }
    #pragma unroll 2
    for (int s = 0; s < TPAD; ++s) {         // v rows >=49 are zero: safe
      u64 b0 = lds64(&qkv[s*QP + 2*CDIM + 2*cp0]);
      u64 b1 = lds64(&qkv[s*QP + 2*CDIM + 2*cp1]);
      #pragma unroll
      for (int i = 0; i < 7; ++i) {
        int t = r0 + i;
        ffma2(acc[i][0], splat2(attn[(h0*TPAD + t)*AP + s]), b0);
        ffma2(acc[i][1], splat2(attn[(h1*TPAD + t)*AP + s]), b1);
      }
    }
    #pragma unroll
    for (int i = 0; i < 7; ++i) {
      int r = r0 + i;
      #pragma unroll
      for (int j = 0; j < 2; ++j) {
        int cp = (j == 0) ? cp0 : cp1;
        float lo, hi; unpk2(acc[i][j], lo, hi);
        __nv_bfloat16 hl=__float2bfloat16_rn(lo), hh=__float2bfloat16_rn(hi);
        u32 hwv = (u32)__bfloat16_as_ushort(hl) | ((u32)__bfloat16_as_ushort(hh)<<16);
        u32 lwv = pkbf(lo-__bfloat162float(hl), hi-__bfloat162float(hh));
        u32 off = (u32)(r*TP + 2*cp)*2;
        *reinterpret_cast<u32*>(xh + off) = hwv;
        *reinterpret_cast<u32*>(xl + off) = lwv;
      }
    }
  }
  __syncthreads();

  // ---- stage 4: out = o2 @ proj_w^T + b via HMMA --------------------------
  stage_w(wh, wl, proj_w, tid);              // attn region dead now
  __syncthreads();
  {
    float acc[2][4][4];
    #pragma unroll
    for (int mt=0;mt<2;++mt)
      #pragma unroll
      for (int nt=0;nt<4;++nt)
        #pragma unroll
        for (int e=0;e<4;++e) acc[mt][nt][e] = 0.f;

    mma_gemm(aHs, aLs, bHs, bLs, wm, wn, lr, lk, br, bk, acc);

    #pragma unroll
    for (int mt = 0; mt < 2; ++mt)
      #pragma unroll
      for (int nt = 0; nt < 4; ++nt) {
        int c  = wn*32 + nt*8 + qc*2;
        float2 bb = __ldg(reinterpret_cast<const float2*>(proj_b + c));
        int r1 = wm*32 + mt*16 + quad, r2 = r1 + 8;
        if (r1 < T49)
          *reinterpret_cast<float2*>(&o_s[r1*OP + c]) =
              make_float2(acc[mt][nt][0]+bb.x, acc[mt][nt][1]+bb.y);
        if (r2 < T49)
          *reinterpret_cast<float2*>(&o_s[r2*OP + c]) =
              make_float2(acc[mt][nt][2]+bb.x, acc[mt][nt][3]+bb.y);
      }
  }
  __syncthreads();

  // ---- coalesced store ----------------------------------------------------
  {
    float4* og = reinterpret_cast<float4*>(out + (size_t)b*(T49*CDIM));
    #pragma unroll
    for (int it = 0; it < 7; ++it) {
      int e4 = tid + it*256;
      if (e4 < T49*32) {
        int r = e4 >> 5, c4 = (e4 & 31)*4;
        og[e4] = *reinterpret_cast<const float4*>(&o_s[r*OP + c4]);
      }
    }
  }
}

extern "C" void kernel_launch(void* const* d_in, const int* in_sizes, int n_in,
                              void* d_out, int out_size)
{
  const float* x      = (const float*)d_in[0];
  const float* mask   = (const float*)d_in[1];
  const float* qkv_w  = (const float*)d_in[2];
  const float* qkv_b  = (const float*)d_in[3];
  const float* proj_w = (const float*)d_in[4];
  const float* proj_b = (const float*)d_in[5];
  const float* btab   = (const float*)d_in[6];
  float* out = (float*)d_out;

  int B = in_sizes[0] / (T49*CDIM);   // 8192 windows

  cudaFuncSetAttribute(wattn_kernel,
                       cudaFuncAttributeMaxDynamicSharedMemorySize, SMEM_BYTES);
  wattn_kernel<<<B, 256, SMEM_BYTES>>>(x, mask, qkv_w, qkv_b,
                                       proj_w, proj_b, btab, out);
}

// round 10
// speedup vs baseline: 1.8282x; 1.2372x over previous
#include <cuda_runtime.h>
#include <cuda_bf16.h>

typedef unsigned long long u64;
typedef unsigned int u32;

#define T49   49
#define CDIM  128
#define NH    4
#define TP    136      /* main bf16 tile pitch (272B/row, 4-bank row shift) */
#define ATP   72       /* attn bf16 tile pitch (144B/row)                   */
#define OP    132      /* o_s fp32 pitch                                    */

/* byte offsets; aliases noted */
#define XH_OFF  0                  /* x hi  -> v hi  (after QKV ch2)  */
#define XL_OFF  17408              /* x lo  -> v lo                   */
#define QH_OFF  34816              /* q hi  -> o2 hi (after 3a)       */
#define QL_OFF  52224
#define KH_OFF  69632              /* k hi  -> o_s fp32 (after 3a)    */
#define KL_OFF  87040
#define OS_OFF  69632
#define WH_OFF  104448             /* W hi  -> attn hi (between GEMMs)*/
#define WL_OFF  139264
#define AH_OFF  104448             /* attnH: 4 heads x 9216B          */
#define AL_OFF  (104448+36864)     /* attnL                           */
#define SMEM_BYTES 178176

// ---------------- helpers --------------------------------------------------
__device__ __forceinline__ u32 smem_u32(const void* p){
  u32 a; asm("{ .reg .u64 t; cvta.to.shared.u64 t, %1; cvt.u32.u64 %0, t; }"
             : "=r"(a) : "l"(p));
  return a;
}
__device__ __forceinline__ u32 pkbf(float a, float b){
  __nv_bfloat16 x=__float2bfloat16_rn(a), y=__float2bfloat16_rn(b);
  return (u32)__bfloat16_as_ushort(x) | ((u32)__bfloat16_as_ushort(y)<<16);
}
// split 2 fp32 -> bf16-hi u32 + bf16-residual u32
__device__ __forceinline__ void split_store2(char* th_, char* tl_, u32 off,
                                             float a, float b){
  __nv_bfloat16 ha=__float2bfloat16_rn(a), hb=__float2bfloat16_rn(b);
  u32 hw = (u32)__bfloat16_as_ushort(ha) | ((u32)__bfloat16_as_ushort(hb)<<16);
  u32 lw = pkbf(a-__bfloat162float(ha), b-__bfloat162float(hb));
  *reinterpret_cast<u32*>(th_+off) = hw;
  *reinterpret_cast<u32*>(tl_+off) = lw;
}
__device__ __forceinline__ void split_store4(char* th_, char* tl_, u32 off, float4 v){
  __nv_bfloat16 h0=__float2bfloat16_rn(v.x), h1=__float2bfloat16_rn(v.y);
  __nv_bfloat16 h2=__float2bfloat16_rn(v.z), h3=__float2bfloat16_rn(v.w);
  u64 hw = (u64)((u32)__bfloat16_as_ushort(h0)|((u32)__bfloat16_as_ushort(h1)<<16))
         | ((u64)((u32)__bfloat16_as_ushort(h2)|((u32)__bfloat16_as_ushort(h3)<<16))<<32);
  u64 lw = (u64)pkbf(v.x-__bfloat162float(h0), v.y-__bfloat162float(h1))
         | ((u64)pkbf(v.z-__bfloat162float(h2), v.w-__bfloat162float(h3))<<32);
  *reinterpret_cast<u64*>(th_+off) = hw;
  *reinterpret_cast<u64*>(tl_+off) = lw;
}
// stage 128x128 fp32 weight block (row = out-channel n, col = k) into bf16 tiles
__device__ __forceinline__ void stage_w(char* dh, char* dl, const float* wg, int tid){
  #pragma unroll
  for (int it = 0; it < 16; ++it){
    int e4 = tid + it*256;
    int n = e4>>5, k4 = (e4&31)*4;
    float4 v = __ldg(reinterpret_cast<const float4*>(wg + n*CDIM) + (e4&31));
    split_store4(dh, dl, (u32)(n*TP + k4)*2, v);
  }
}
// ---------------- mma.sync / ldmatrix --------------------------------------
__device__ __forceinline__ void ldmA(u32* r, u32 addr){
  asm volatile("ldmatrix.sync.aligned.m8n8.x4.shared.b16 {%0,%1,%2,%3}, [%4];"
    : "=r"(r[0]),"=r"(r[1]),"=r"(r[2]),"=r"(r[3]) : "r"(addr));
}
__device__ __forceinline__ void ldmB(u32* r, u32 addr){
  asm volatile("ldmatrix.sync.aligned.m8n8.x2.shared.b16 {%0,%1}, [%2];"
    : "=r"(r[0]),"=r"(r[1]) : "r"(addr));
}
__device__ __forceinline__ void ldmBt(u32* r, u32 addr){
  asm volatile("ldmatrix.sync.aligned.m8n8.x2.trans.shared.b16 {%0,%1}, [%2];"
    : "=r"(r[0]),"=r"(r[1]) : "r"(addr));
}
__device__ __forceinline__ void mma16816(float* c, const u32* a, const u32* b){
  asm volatile("mma.sync.aligned.m16n8k16.row.col.f32.bf16.bf16.f32 "
    "{%0,%1,%2,%3}, {%4,%5,%6,%7}, {%8,%9}, {%0,%1,%2,%3};"
    : "+f"(c[0]),"+f"(c[1]),"+f"(c[2]),"+f"(c[3])
    : "r"(a[0]),"r"(a[1]),"r"(a[2]),"r"(a[3]), "r"(b[0]),"r"(b[1]));
}
// 64x128x128 GEMM, 3-term split bf16; warp (wm,wn) owns 32x32 of output
__device__ __forceinline__ void mma_gemm(
    u32 aH, u32 aL, u32 bH, u32 bL,
    int wm, int wn, int lr, int lk, int br, int bk, float acc[2][4][4])
{
  #pragma unroll
  for (int k0 = 0; k0 < 128; k0 += 16){
    u32 ah[2][4], al[2][4], bh[4][2], bl[4][2];
    #pragma unroll
    for (int mt = 0; mt < 2; ++mt){
      u32 ar = (u32)((wm*32 + mt*16 + lr)*TP + k0 + lk*8)*2;
      ldmA(ah[mt], aH + ar);
      ldmA(al[mt], aL + ar);
    }
    #pragma unroll
    for (int nt = 0; nt < 4; ++nt){
      u32 brr = (u32)((wn*32 + nt*8 + br)*TP + k0 + bk*8)*2;
      ldmB(bh[nt], bH + brr);
      ldmB(bl[nt], bL + brr);
    }
    #pragma unroll
    for (int mt = 0; mt < 2; ++mt)
      #pragma unroll
      for (int nt = 0; nt < 4; ++nt){
        mma16816(acc[mt][nt], ah[mt], bh[nt]);
        mma16816(acc[mt][nt], ah[mt], bl[nt]);
        mma16816(acc[mt][nt], al[mt], bh[nt]);
      }
  }
}
__device__ __forceinline__ float fin_attn(int t, int s, float v, int h,
    const float* __restrict__ bt, const float* __restrict__ mrow){
  if (t >= T49 || s >= T49) return 0.f;
  int th = t/7, tw = t - th*7, sh = s/7, sw = s - sh*7;
  int rel = (th - sh + 6)*13 + (tw - sw + 6);
  return v + __ldg(&bt[rel*NH + h]) + __ldg(&mrow[t*T49 + s]);
}

__global__ void __launch_bounds__(256, 1)
wattn_kernel(const float* __restrict__ x, const float* __restrict__ mask,
             const float* __restrict__ qkv_w, const float* __restrict__ qkv_b,
             const float* __restrict__ proj_w, const float* __restrict__ proj_b,
             const float* __restrict__ bias_table, float* __restrict__ out)
{
  extern __shared__ char smc[];
  const u32 sm0 = smem_u32(smc);

  const int b   = blockIdx.x;
  const int tid = threadIdx.x;
  const int tx  = tid & 31;
  const int w   = tid >> 5;                 // warp 0..7
  const int lr = tx & 15, lk = tx >> 4;     // A ldmatrix roles
  const int br = tx & 7,  bk = (tx >> 3) & 1;
  const int quad = tx >> 2, qc = tx & 3;    // D fragment roles
  const int wm = w & 1, wn = w >> 1;        // GEMM warp grid 2x4

  // ---- stage 1: x -> bf16 hi/lo A tiles; Wqkv ch0 -> W tiles --------------
  {
    const float4* xg = reinterpret_cast<const float4*>(x + (size_t)b*(T49*CDIM));
    #pragma unroll
    for (int it = 0; it < 7; ++it) {
      int e4 = tid + it*256;
      if (e4 < T49*32) {
        int r = e4 >> 5, c4 = (e4 & 31)*4;
        split_store4(smc+XH_OFF, smc+XL_OFF, (u32)(r*TP + c4)*2, __ldg(xg + e4));
      }
    }
    stage_w(smc+WH_OFF, smc+WL_OFF, qkv_w, tid);
  }
  __syncthreads();

  // ---- stage 2: QKV GEMM, epilogue splits straight into q/k/v tiles -------
  const float scale = 0.17677669529663687f;     // 32^-0.5 (folded into q)
  #pragma unroll 1
  for (int ch = 0; ch < 3; ++ch) {
    float acc[2][4][4];
    #pragma unroll
    for (int mt=0;mt<2;++mt)
      #pragma unroll
      for (int nt=0;nt<4;++nt)
        #pragma unroll
        for (int e=0;e<4;++e) acc[mt][nt][e] = 0.f;

    mma_gemm(sm0+XH_OFF, sm0+XL_OFF, sm0+WH_OFF, sm0+WL_OFF,
             wm, wn, lr, lk, br, bk, acc);
    __syncthreads();                      // ch2: all A reads done before v->x alias

    char* dh = smc + ((ch==0)?QH_OFF:(ch==1)?KH_OFF:XH_OFF);
    char* dl = smc + ((ch==0)?QL_OFF:(ch==1)?KL_OFF:XL_OFF);
    #pragma unroll
    for (int mt = 0; mt < 2; ++mt)
      #pragma unroll
      for (int nt = 0; nt < 4; ++nt) {
        int c  = wn*32 + nt*8 + qc*2;
        float2 bb = __ldg(reinterpret_cast<const float2*>(qkv_b + ch*CDIM + c));
        int r1 = wm*32 + mt*16 + quad, r2 = r1 + 8;
        float v0 = (r1 < T49) ? acc[mt][nt][0] + bb.x : 0.f;
        float v1 = (r1 < T49) ? acc[mt][nt][1] + bb.y : 0.f;
        float v2 = (r2 < T49) ? acc[mt][nt][2] + bb.x : 0.f;
        float v3 = (r2 < T49) ? acc[mt][nt][3] + bb.y : 0.f;
        if (ch == 0) { v0*=scale; v1*=scale; v2*=scale; v3*=scale; }
        split_store2(dh, dl, (u32)(r1*TP + c)*2, v0, v1);
        split_store2(dh, dl, (u32)(r2*TP + c)*2, v2, v3);
      }
    __syncthreads();
    if (ch < 2) {
      stage_w(smc+WH_OFF, smc+WL_OFF, qkv_w + (ch+1)*CDIM*CDIM, tid);
      __syncthreads();
    }
  }

  // ---- stage 3a: attn = q.k^T + bias + mask via HMMA ----------------------
  {
    const float* mrow = mask + (size_t)(b & 63)*(T49*T49);
    const int h = w >> 1, wm2 = w & 1;       // 4 heads x 2 row-halves
    char* ahc = smc + AH_OFF + h*9216;
    char* alc = smc + AL_OFF + h*9216;
    #pragma unroll 1
    for (int half = 0; half < 2; ++half) {   // 32 s-cols per pass
      float acc[2][4][4];
      #pragma unroll
      for (int mt=0;mt<2;++mt)
        #pragma unroll
        for (int nt=0;nt<4;++nt)
          #pragma unroll
          for (int e=0;e<4;++e) acc[mt][nt][e] = 0.f;

      #pragma unroll
      for (int k0 = 0; k0 < 32; k0 += 16) {
        u32 ah_[2][4], al_[2][4], bh_[4][2], bl_[4][2];
        #pragma unroll
        for (int mt = 0; mt < 2; ++mt){
          u32 ar = (u32)((wm2*32 + mt*16 + lr)*TP + h*32 + k0 + lk*8)*2;
          ldmA(ah_[mt], sm0+QH_OFF + ar);
          ldmA(al_[mt], sm0+QL_OFF + ar);
        }
        #pragma unroll
        for (int nt = 0; nt < 4; ++nt){
          u32 brr = (u32)((half*32 + nt*8 + br)*TP + h*32 + k0 + bk*8)*2;
          ldmB(bh_[nt], sm0+KH_OFF + brr);
          ldmB(bl_[nt], sm0+KL_OFF + brr);
        }
        #pragma unroll
        for (int mt = 0; mt < 2; ++mt)
          #pragma unroll
          for (int nt = 0; nt < 4; ++nt){
            mma16816(acc[mt][nt], ah_[mt], bh_[nt]);
            mma16816(acc[mt][nt], ah_[mt], bl_[nt]);
            mma16816(acc[mt][nt], al_[mt], bh_[nt]);
          }
      }
      #pragma unroll
      for (int mt = 0; mt < 2; ++mt) {
        int r1 = wm2*32 + mt*16 + quad, r2 = r1 + 8;
        #pragma unroll
        for (int nt = 0; nt < 4; ++nt) {
          int s0c = half*32 + nt*8 + qc*2;
          float v00 = fin_attn(r1, s0c,   acc[mt][nt][0], h, bias_table, mrow);
          float v01 = fin_attn(r1, s0c+1, acc[mt][nt][1], h, bias_table, mrow);
          float v10 = fin_attn(r2, s0c,   acc[mt][nt][2], h, bias_table, mrow);
          float v11 = fin_attn(r2, s0c+1, acc[mt][nt][3], h, bias_table, mrow);
          split_store2(ahc, alc, (u32)(r1*ATP + s0c)*2, v00, v01);
          split_store2(ahc, alc, (u32)(r2*ATP + s0c)*2, v10, v11);
        }
      }
    }
  }
  __syncthreads();

  // ---- stage 3b: o2 = attn @ v via HMMA (v through ldmatrix.trans) --------
  {
    const int h = w >> 1, wm2 = w & 1;
    const u32 aHh = sm0 + AH_OFF + h*9216, aLh = sm0 + AL_OFF + h*9216;
    const int lr16 = tx & 15;
    float acc[2][4][4];
    #pragma unroll
    for (int mt=0;mt<2;++mt)
      #pragma unroll
      for (int nt=0;nt<4;++nt)
        #pragma unroll
        for (int e=0;e<4;++e) acc[mt][nt][e] = 0.f;

    #pragma unroll
    for (int s0 = 0; s0 < 64; s0 += 16) {
      u32 ah_[2][4], al_[2][4], bh_[4][2], bl_[4][2];
      #pragma unroll
      for (int mt = 0; mt < 2; ++mt){
        u32 ar = (u32)((wm2*32 + mt*16 + lr)*ATP + s0 + lk*8)*2;
        ldmA(ah_[mt], aHh + ar);
        ldmA(al_[mt], aLh + ar);
      }
      #pragma unroll
      for (int nt = 0; nt < 4; ++nt){
        u32 brr = (u32)((s0 + lr16)*TP + h*32 + nt*8)*2;
        ldmBt(bh_[nt], sm0+XH_OFF + brr);   // v aliased over x
        ldmBt(bl_[nt], sm0+XL_OFF + brr);
      }
      #pragma unroll
      for (int mt = 0; mt < 2; ++mt)
        #pragma unroll
        for (int nt = 0; nt < 4; ++nt){
          mma16816(acc[mt][nt], ah_[mt], bh_[nt]);
          mma16816(acc[mt][nt], ah_[mt], bl_[nt]);
          mma16816(acc[mt][nt], al_[mt], bh_[nt]);
        }
    }
    __syncthreads();                        // attn reads done before o2->q alias
    #pragma unroll
    for (int mt = 0; mt < 2; ++mt) {
      int r1 = wm2*32 + mt*16 + quad, r2 = r1 + 8;
      #pragma unroll
      for (int nt = 0; nt < 4; ++nt) {
        int c = h*32 + nt*8 + qc*2;
        split_store2(smc+QH_OFF, smc+QL_OFF, (u32)(r1*TP + c)*2,
                     acc[mt][nt][0], acc[mt][nt][1]);
        split_store2(smc+QH_OFF, smc+QL_OFF, (u32)(r2*TP + c)*2,
                     acc[mt][nt][2], acc[mt][nt][3]);
      }
    }
  }
  __syncthreads();

  // ---- stage 4: out = o2 @ proj_w^T + b via HMMA --------------------------
  stage_w(smc+WH_OFF, smc+WL_OFF, proj_w, tid);   // attn region dead
  __syncthreads();
  {
    float acc[2][4][4];
    #pragma unroll
    for (int mt=0;mt<2;++mt)
      #pragma unroll
      for (int nt=0;nt<4;++nt)
        #pragma unroll
        for (int e=0;e<4;++e) acc[mt][nt][e] = 0.f;

    mma_gemm(sm0+QH_OFF, sm0+QL_OFF, sm0+WH_OFF, sm0+WL_OFF,
             wm, wn, lr, lk, br, bk, acc);

    float* o_s = reinterpret_cast<float*>(smc + OS_OFF);   // k tiles dead
    #pragma unroll
    for (int mt = 0; mt < 2; ++mt)
      #pragma unroll
      for (int nt = 0; nt < 4; ++nt) {
        int c  = wn*32 + nt*8 + qc*2;
        float2 bb = __ldg(reinterpret_cast<const float2*>(proj_b + c));
        int r1 = wm*32 + mt*16 + quad, r2 = r1 + 8;
        if (r1 < T49)
          *reinterpret_cast<float2*>(&o_s[r1*OP + c]) =
              make_float2(acc[mt][nt][0]+bb.x, acc[mt][nt][1]+bb.y);
        if (r2 < T49)
          *reinterpret_cast<float2*>(&o_s[r2*OP + c]) =
              make_float2(acc[mt][nt][2]+bb.x, acc[mt][nt][3]+bb.y);
      }
  }
  __syncthreads();

  // ---- coalesced store ----------------------------------------------------
  {
    const float* o_s = reinterpret_cast<const float*>(smc + OS_OFF);
    float4* og = reinterpret_cast<float4*>(out + (size_t)b*(T49*CDIM));
    #pragma unroll
    for (int it = 0; it < 7; ++it) {
      int e4 = tid + it*256;
      if (e4 < T49*32) {
        int r = e4 >> 5, c4 = (e4 & 31)*4;
        og[e4] = *reinterpret_cast<const float4*>(&o_s[r*OP + c4]);
      }
    }
  }
}

extern "C" void kernel_launch(void* const* d_in, const int* in_sizes, int n_in,
                              void* d_out, int out_size)
{
  const float* x      = (const float*)d_in[0];
  const float* mask   = (const float*)d_in[1];
  const float* qkv_w  = (const float*)d_in[2];
  const float* qkv_b  = (const float*)d_in[3];
  const float* proj_w = (const float*)d_in[4];
  const float* proj_b = (const float*)d_in[5];
  const float* btab   = (const float*)d_in[6];
  float* out = (float*)d_out;

  int B = in_sizes[0] / (T49*CDIM);   // 8192 windows

  cudaFuncSetAttribute(wattn_kernel,
                       cudaFuncAttributeMaxDynamicSharedMemorySize, SMEM_BYTES);
  wattn_kernel<<<B, 256, SMEM_BYTES>>>(x, mask, qkv_w, qkv_b,
                                       proj_w, proj_b, btab, out);
}

// round 11
// speedup vs baseline: 1.8316x; 1.0018x over previous
#include <cuda_runtime.h>
#include <cuda_bf16.h>

typedef unsigned long long u64;
typedef unsigned int u32;

#define T49   49
#define CDIM  128
#define NH    4
#define TP    136      /* main bf16 tile pitch (272B/row) */
#define ATP   72       /* attn bf16 tile pitch (144B/row) */
#define OP    132      /* o_s fp32 pitch                  */

/* byte offsets; aliases noted */
#define XH_OFF  0                  /* x hi  -> v hi  (after QKV ch2)  */
#define XL_OFF  17408              /* x lo  -> v lo                   */
#define QH_OFF  34816              /* q hi  -> o2 hi (after 3a)       */
#define QL_OFF  52224
#define KH_OFF  69632              /* k hi  -> o_s fp32 (after 3a)    */
#define KL_OFF  87040
#define OS_OFF  69632
#define WH_OFF  104448             /* W hi  -> attn hi (between GEMMs)*/
#define WL_OFF  139264
#define AH_OFF  104448             /* attnH: 4 heads x 9216B          */
#define AL_OFF  (104448+36864)     /* attnL                           */
#define SMEM_BYTES 178176

// ---------------- helpers --------------------------------------------------
__device__ __forceinline__ u32 smem_u32(const void* p){
  u32 a; asm("{ .reg .u64 t; cvta.to.shared.u64 t, %1; cvt.u32.u64 %0, t; }"
             : "=r"(a) : "l"(p));
  return a;
}
__device__ __forceinline__ u32 pkbf(float a, float b){
  __nv_bfloat16 x=__float2bfloat16_rn(a), y=__float2bfloat16_rn(b);
  return (u32)__bfloat16_as_ushort(x) | ((u32)__bfloat16_as_ushort(y)<<16);
}
__device__ __forceinline__ void split_store2(char* th_, char* tl_, u32 off,
                                             float a, float b){
  __nv_bfloat16 ha=__float2bfloat16_rn(a), hb=__float2bfloat16_rn(b);
  u32 hw = (u32)__bfloat16_as_ushort(ha) | ((u32)__bfloat16_as_ushort(hb)<<16);
  u32 lw = pkbf(a-__bfloat162float(ha), b-__bfloat162float(hb));
  *reinterpret_cast<u32*>(th_+off) = hw;
  *reinterpret_cast<u32*>(tl_+off) = lw;
}
__device__ __forceinline__ void split_store4(char* th_, char* tl_, u32 off, float4 v){
  __nv_bfloat16 h0=__float2bfloat16_rn(v.x), h1=__float2bfloat16_rn(v.y);
  __nv_bfloat16 h2=__float2bfloat16_rn(v.z), h3=__float2bfloat16_rn(v.w);
  u64 hw = (u64)((u32)__bfloat16_as_ushort(h0)|((u32)__bfloat16_as_ushort(h1)<<16))
         | ((u64)((u32)__bfloat16_as_ushort(h2)|((u32)__bfloat16_as_ushort(h3)<<16))<<32);
  u64 lw = (u64)pkbf(v.x-__bfloat162float(h0), v.y-__bfloat162float(h1))
         | ((u64)pkbf(v.z-__bfloat162float(h2), v.w-__bfloat162float(h3))<<32);
  *reinterpret_cast<u64*>(th_+off) = hw;
  *reinterpret_cast<u64*>(tl_+off) = lw;
}
// stage 128x128 fp32 weight block (row = out-channel n, col = k) into bf16 tiles
__device__ __forceinline__ void stage_w(char* dh, char* dl, const float* wg, int tid){
  #pragma unroll
  for (int it = 0; it < 8; ++it){
    int e4 = tid + it*512;
    int n = e4>>5, k4 = (e4&31)*4;
    float4 v = __ldg(reinterpret_cast<const float4*>(wg + n*CDIM) + (e4&31));
    split_store4(dh, dl, (u32)(n*TP + k4)*2, v);
  }
}
// ---------------- mma.sync / ldmatrix --------------------------------------
__device__ __forceinline__ void ldmA(u32* r, u32 addr){
  asm volatile("ldmatrix.sync.aligned.m8n8.x4.shared.b16 {%0,%1,%2,%3}, [%4];"
    : "=r"(r[0]),"=r"(r[1]),"=r"(r[2]),"=r"(r[3]) : "r"(addr));
}
__device__ __forceinline__ void ldmB(u32* r, u32 addr){
  asm volatile("ldmatrix.sync.aligned.m8n8.x2.shared.b16 {%0,%1}, [%2];"
    : "=r"(r[0]),"=r"(r[1]) : "r"(addr));
}
__device__ __forceinline__ void ldmBt(u32* r, u32 addr){
  asm volatile("ldmatrix.sync.aligned.m8n8.x2.trans.shared.b16 {%0,%1}, [%2];"
    : "=r"(r[0]),"=r"(r[1]) : "r"(addr));
}
__device__ __forceinline__ void mma16816(float* c, const u32* a, const u32* b){
  asm volatile("mma.sync.aligned.m16n8k16.row.col.f32.bf16.bf16.f32 "
    "{%0,%1,%2,%3}, {%4,%5,%6,%7}, {%8,%9}, {%0,%1,%2,%3};"
    : "+f"(c[0]),"+f"(c[1]),"+f"(c[2]),"+f"(c[3])
    : "r"(a[0]),"r"(a[1]),"r"(a[2]),"r"(a[3]), "r"(b[0]),"r"(b[1]));
}
// 64x128x128 GEMM, 3-term split; warp (wm 0..3, wn 0..3) owns 16x32 of output
__device__ __forceinline__ void mma_gemm16(
    u32 aH, u32 aL, u32 bH, u32 bL,
    int wm, int wn, int lr, int lk, int br, int bk, float acc[4][4])
{
  #pragma unroll
  for (int k0 = 0; k0 < 128; k0 += 16){
    u32 ah[4], al[4], bh[4][2], bl[4][2];
    u32 ar = (u32)((wm*16 + lr)*TP + k0 + lk*8)*2;
    ldmA(ah, aH + ar);
    ldmA(al, aL + ar);
    #pragma unroll
    for (int nt = 0; nt < 4; ++nt){
      u32 brr = (u32)((wn*32 + nt*8 + br)*TP + k0 + bk*8)*2;
      ldmB(bh[nt], bH + brr);
      ldmB(bl[nt], bL + brr);
    }
    #pragma unroll
    for (int nt = 0; nt < 4; ++nt){
      mma16816(acc[nt], ah, bh[nt]);
      mma16816(acc[nt], ah, bl[nt]);
      mma16816(acc[nt], al, bh[nt]);
    }
  }
}
__device__ __forceinline__ float fin_attn(int t, int s, float v, int h,
    const float* __restrict__ bt, const float* __restrict__ mrow){
  if (t >= T49 || s >= T49) return 0.f;
  int th = t/7, tw = t - th*7, sh = s/7, sw = s - sh*7;
  int rel = (th - sh + 6)*13 + (tw - sw + 6);
  return v + __ldg(&bt[rel*NH + h]) + __ldg(&mrow[t*T49 + s]);
}

__global__ void __launch_bounds__(512, 1)
wattn_kernel(const float* __restrict__ x, const float* __restrict__ mask,
             const float* __restrict__ qkv_w, const float* __restrict__ qkv_b,
             const float* __restrict__ proj_w, const float* __restrict__ proj_b,
             const float* __restrict__ bias_table, float* __restrict__ out)
{
  extern __shared__ char smc[];
  const u32 sm0 = smem_u32(smc);

  const int b   = blockIdx.x;
  const int tid = threadIdx.x;
  const int tx  = tid & 31;
  const int w   = tid >> 5;                 // warp 0..15
  const int lr = tx & 15, lk = tx >> 4;     // A ldmatrix roles
  const int br = tx & 7,  bk = (tx >> 3) & 1;
  const int quad = tx >> 2, qc = tx & 3;    // D fragment roles
  const int wm = w & 3, wn = w >> 2;        // GEMM warp grid 4x4

  // ---- stage 1: x -> bf16 hi/lo A tiles; Wqkv ch0 -> W tiles --------------
  {
    const float4* xg = reinterpret_cast<const float4*>(x + (size_t)b*(T49*CDIM));
    #pragma unroll
    for (int it = 0; it < 4; ++it) {
      int e4 = tid + it*512;
      if (e4 < T49*32) {
        int r = e4 >> 5, c4 = (e4 & 31)*4;
        split_store4(smc+XH_OFF, smc+XL_OFF, (u32)(r*TP + c4)*2, __ldg(xg + e4));
      }
    }
    stage_w(smc+WH_OFF, smc+WL_OFF, qkv_w, tid);
  }
  __syncthreads();

  // ---- stage 2: QKV GEMM, epilogue splits straight into q/k/v tiles -------
  const float scale = 0.17677669529663687f;     // 32^-0.5 (folded into q)
  #pragma unroll 1
  for (int ch = 0; ch < 3; ++ch) {
    float acc[4][4];
    #pragma unroll
    for (int nt=0;nt<4;++nt)
      #pragma unroll
      for (int e=0;e<4;++e) acc[nt][e] = 0.f;

    mma_gemm16(sm0+XH_OFF, sm0+XL_OFF, sm0+WH_OFF, sm0+WL_OFF,
               wm, wn, lr, lk, br, bk, acc);
    __syncthreads();                  // ch2: A reads done before v->x alias

    char* dh = smc + ((ch==0)?QH_OFF:(ch==1)?KH_OFF:XH_OFF);
    char* dl = smc + ((ch==0)?QL_OFF:(ch==1)?KL_OFF:XL_OFF);
    #pragma unroll
    for (int nt = 0; nt < 4; ++nt) {
      int c  = wn*32 + nt*8 + qc*2;
      float2 bb = __ldg(reinterpret_cast<const float2*>(qkv_b + ch*CDIM + c));
      int r1 = wm*16 + quad, r2 = r1 + 8;
      float v0 = (r1 < T49) ? acc[nt][0] + bb.x : 0.f;
      float v1 = (r1 < T49) ? acc[nt][1] + bb.y : 0.f;
      float v2 = (r2 < T49) ? acc[nt][2] + bb.x : 0.f;
      float v3 = (r2 < T49) ? acc[nt][3] + bb.y : 0.f;
      if (ch == 0) { v0*=scale; v1*=scale; v2*=scale; v3*=scale; }
      split_store2(dh, dl, (u32)(r1*TP + c)*2, v0, v1);
      split_store2(dh, dl, (u32)(r2*TP + c)*2, v2, v3);
    }
    __syncthreads();
    if (ch < 2) {
      stage_w(smc+WH_OFF, smc+WL_OFF, qkv_w + (ch+1)*CDIM*CDIM, tid);
      __syncthreads();
    }
  }

  // ---- stage 3a: attn = q.k^T + bias + mask via HMMA ----------------------
  // 16 warps = 4 heads x 2 row-halves x 2 col-halves, each a 32x32 block
  {
    const float* mrow = mask + (size_t)(b & 63)*(T49*T49);
    const int h = w >> 2, wm2 = (w >> 1) & 1, half = w & 1;
    char* ahc = smc + AH_OFF + h*9216;
    char* alc = smc + AL_OFF + h*9216;
    float acc[2][4][4];
    #pragma unroll
    for (int mt=0;mt<2;++mt)
      #pragma unroll
      for (int nt=0;nt<4;++nt)
        #pragma unroll
        for (int e=0;e<4;++e) acc[mt][nt][e] = 0.f;

    #pragma unroll
    for (int k0 = 0; k0 < 32; k0 += 16) {
      u32 ah_[2][4], al_[2][4], bh_[4][2], bl_[4][2];
      #pragma unroll
      for (int mt = 0; mt < 2; ++mt){
        u32 ar = (u32)((wm2*32 + mt*16 + lr)*TP + h*32 + k0 + lk*8)*2;
        ldmA(ah_[mt], sm0+QH_OFF + ar);
        ldmA(al_[mt], sm0+QL_OFF + ar);
      }
      #pragma unroll
      for (int nt = 0; nt < 4; ++nt){
        u32 brr = (u32)((half*32 + nt*8 + br)*TP + h*32 + k0 + bk*8)*2;
        ldmB(bh_[nt], sm0+KH_OFF + brr);
        ldmB(bl_[nt], sm0+KL_OFF + brr);
      }
      #pragma unroll
      for (int mt = 0; mt < 2; ++mt)
        #pragma unroll
        for (int nt = 0; nt < 4; ++nt){
          mma16816(acc[mt][nt], ah_[mt], bh_[nt]);
          mma16816(acc[mt][nt], ah_[mt], bl_[nt]);
          mma16816(acc[mt][nt], al_[mt], bh_[nt]);
        }
    }
    #pragma unroll
    for (int mt = 0; mt < 2; ++mt) {
      int r1 = wm2*32 + mt*16 + quad, r2 = r1 + 8;
      #pragma unroll
      for (int nt = 0; nt < 4; ++nt) {
        int s0c = half*32 + nt*8 + qc*2;
        float v00 = fin_attn(r1, s0c,   acc[mt][nt][0], h, bias_table, mrow);
        float v01 = fin_attn(r1, s0c+1, acc[mt][nt][1], h, bias_table, mrow);
        float v10 = fin_attn(r2, s0c,   acc[mt][nt][2], h, bias_table, mrow);
        float v11 = fin_attn(r2, s0c+1, acc[mt][nt][3], h, bias_table, mrow);
        split_store2(ahc, alc, (u32)(r1*ATP + s0c)*2, v00, v01);
        split_store2(ahc, alc, (u32)(r2*ATP + s0c)*2, v10, v11);
      }
    }
  }
  __syncthreads();

  // ---- stage 3b: o2 = attn @ v via HMMA (v through ldmatrix.trans) --------
  // 16 warps = 4 heads x 2 row-halves x 2 col-groups (32x16 each)
  {
    const int h = w >> 2, wm2 = (w >> 1) & 1, cg = w & 1;
    const u32 aHh = sm0 + AH_OFF + h*9216, aLh = sm0 + AL_OFF + h*9216;
    const int lr16 = tx & 15;
    float acc[2][2][4];
    #pragma unroll
    for (int mt=0;mt<2;++mt)
      #pragma unroll
      for (int nt=0;nt<2;++nt)
        #pragma unroll
        for (int e=0;e<4;++e) acc[mt][nt][e] = 0.f;

    #pragma unroll
    for (int s0 = 0; s0 < 64; s0 += 16) {
      u32 ah_[2][4], al_[2][4], bh_[2][2], bl_[2][2];
      #pragma unroll
      for (int mt = 0; mt < 2; ++mt){
        u32 ar = (u32)((wm2*32 + mt*16 + lr)*ATP + s0 + lk*8)*2;
        ldmA(ah_[mt], aHh + ar);
        ldmA(al_[mt], aLh + ar);
      }
      #pragma unroll
      for (int nt = 0; nt < 2; ++nt){
        u32 brr = (u32)((s0 + lr16)*TP + h*32 + cg*16 + nt*8)*2;
        ldmBt(bh_[nt], sm0+XH_OFF + brr);   // v aliased over x
        ldmBt(bl_[nt], sm0+XL_OFF + brr);
      }
      #pragma unroll
      for (int mt = 0; mt < 2; ++mt)
        #pragma unroll
        for (int nt = 0; nt < 2; ++nt){
          mma16816(acc[mt][nt], ah_[mt], bh_[nt]);
          mma16816(acc[mt][nt], ah_[mt], bl_[nt]);
          mma16816(acc[mt][nt], al_[mt], bh_[nt]);
        }
    }
    __syncthreads();                        // attn reads done before o2->q alias
    #pragma unroll
    for (int mt = 0; mt < 2; ++mt) {
      int r1 = wm2*32 + mt*16 + quad, r2 = r1 + 8;
      #pragma unroll
      for (int nt = 0; nt < 2; ++nt) {
        int c = h*32 + cg*16 + nt*8 + qc*2;
        split_store2(smc+QH_OFF, smc+QL_OFF, (u32)(r1*TP + c)*2,
                     acc[mt][nt][0], acc[mt][nt][1]);
        split_store2(smc+QH_OFF, smc+QL_OFF, (u32)(r2*TP + c)*2,
                     acc[mt][nt][2], acc[mt][nt][3]);
      }
    }
  }
  __syncthreads();

  // ---- stage 4: out = o2 @ proj_w^T + b via HMMA --------------------------
  stage_w(smc+WH_OFF, smc+WL_OFF, proj_w, tid);   // attn region dead
  __syncthreads();
  {
    float acc[4][4];
    #pragma unroll
    for (int nt=0;nt<4;++nt)
      #pragma unroll
      for (int e=0;e<4;++e) acc[nt][e] = 0.f;

    mma_gemm16(sm0+QH_OFF, sm0+QL_OFF, sm0+WH_OFF, sm0+WL_OFF,
               wm, wn, lr, lk, br, bk, acc);

    float* o_s = reinterpret_cast<float*>(smc + OS_OFF);   // k tiles dead
    #pragma unroll
    for (int nt = 0; nt < 4; ++nt) {
      int c  = wn*32 + nt*8 + qc*2;
      float2 bb = __ldg(reinterpret_cast<const float2*>(proj_b + c));
      int r1 = wm*16 + quad, r2 = r1 + 8;
      if (r1 < T49)
        *reinterpret_cast<float2*>(&o_s[r1*OP + c]) =
            make_float2(acc[nt][0]+bb.x, acc[nt][1]+bb.y);
      if (r2 < T49)
        *reinterpret_cast<float2*>(&o_s[r2*OP + c]) =
            make_float2(acc[nt][2]+bb.x, acc[nt][3]+bb.y);
    }
  }
  __syncthreads();

  // ---- coalesced store ----------------------------------------------------
  {
    const float* o_s = reinterpret_cast<const float*>(smc + OS_OFF);
    float4* og = reinterpret_cast<float4*>(out + (size_t)b*(T49*CDIM));
    #pragma unroll
    for (int it = 0; it < 4; ++it) {
      int e4 = tid + it*512;
      if (e4 < T49*32) {
        int r = e4 >> 5, c4 = (e4 & 31)*4;
        og[e4] = *reinterpret_cast<const float4*>(&o_s[r*OP + c4]);
      }
    }
  }
}

extern "C" void kernel_launch(void* const* d_in, const int* in_sizes, int n_in,
                              void* d_out, int out_size)
{
  const float* x      = (const float*)d_in[0];
  const float* mask   = (const float*)d_in[1];
  const float* qkv_w  = (const float*)d_in[2];
  const float* qkv_b  = (const float*)d_in[3];
  const float* proj_w = (const float*)d_in[4];
  const float* proj_b = (const float*)d_in[5];
  const float* btab   = (const float*)d_in[6];
  float* out = (float*)d_out;

  int B = in_sizes[0] / (T49*CDIM);   // 8192 windows

  cudaFuncSetAttribute(wattn_kernel,
                       cudaFuncAttributeMaxDynamicSharedMemorySize, SMEM_BYTES);
  wattn_kernel<<<B, 512, SMEM_BYTES>>>(x, mask, qkv_w, qkv_b,
                                       proj_w, proj_b, btab, out);
}

// round 12
// speedup vs baseline: 1.9525x; 1.0660x over previous
#include <cuda_runtime.h>
#include <cuda_bf16.h>

typedef unsigned long long u64;
typedef unsigned int u32;

#define T49   49
#define CDIM  128
#define NH    4
#define TP    136      /* main bf16 tile pitch (272B/row) */
#define OP    132      /* o_s fp32 pitch                  */

/* byte offsets; aliases noted */
#define XH_OFF  0                  /* x hi  -> v hi  (after QKV ch2)  */
#define XL_OFF  17408              /* x lo  -> v lo                   */
#define QH_OFF  34816              /* q hi  -> o2 hi (after attn)     */
#define QL_OFF  52224
#define KH_OFF  69632              /* k hi  -> o_s fp32 (after attn)  */
#define KL_OFF  87040
#define OS_OFF  69632
#define WH_OFF  104448             /* W hi/lo                         */
#define WL_OFF  139264
#define BM_OFF  174080             /* bias+mask table [49][49][4] f32 */
#define SMEM_BYTES (174080+38416)  /* 212496 */

// ---------------- helpers --------------------------------------------------
__device__ __forceinline__ u32 smem_u32(const void* p){
  u32 a; asm("{ .reg .u64 t; cvta.to.shared.u64 t, %1; cvt.u32.u64 %0, t; }"
             : "=r"(a) : "l"(p));
  return a;
}
__device__ __forceinline__ u32 pkbf(float a, float b){
  __nv_bfloat16 x=__float2bfloat16_rn(a), y=__float2bfloat16_rn(b);
  return (u32)__bfloat16_as_ushort(x) | ((u32)__bfloat16_as_ushort(y)<<16);
}
__device__ __forceinline__ void pksplit(float a, float b, u32 &hw, u32 &lw){
  __nv_bfloat16 ha=__float2bfloat16_rn(a), hb=__float2bfloat16_rn(b);
  hw = (u32)__bfloat16_as_ushort(ha) | ((u32)__bfloat16_as_ushort(hb)<<16);
  lw = pkbf(a-__bfloat162float(ha), b-__bfloat162float(hb));
}
__device__ __forceinline__ void split_store2(char* th_, char* tl_, u32 off,
                                             float a, float b){
  u32 hw, lw; pksplit(a, b, hw, lw);
  *reinterpret_cast<u32*>(th_+off) = hw;
  *reinterpret_cast<u32*>(tl_+off) = lw;
}
__device__ __forceinline__ void split_store4(char* th_, char* tl_, u32 off, float4 v){
  __nv_bfloat16 h0=__float2bfloat16_rn(v.x), h1=__float2bfloat16_rn(v.y);
  __nv_bfloat16 h2=__float2bfloat16_rn(v.z), h3=__float2bfloat16_rn(v.w);
  u64 hw = (u64)((u32)__bfloat16_as_ushort(h0)|((u32)__bfloat16_as_ushort(h1)<<16))
         | ((u64)((u32)__bfloat16_as_ushort(h2)|((u32)__bfloat16_as_ushort(h3)<<16))<<32);
  u64 lw = (u64)pkbf(v.x-__bfloat162float(h0), v.y-__bfloat162float(h1))
         | ((u64)pkbf(v.z-__bfloat162float(h2), v.w-__bfloat162float(h3))<<32);
  *reinterpret_cast<u64*>(th_+off) = hw;
  *reinterpret_cast<u64*>(tl_+off) = lw;
}
// stage 128x128 fp32 weight block (row = out-channel n, col = k) into bf16 tiles
__device__ __forceinline__ void stage_w(char* dh, char* dl, const float* wg, int tid){
  #pragma unroll
  for (int it = 0; it < 8; ++it){
    int e4 = tid + it*512;
    int n = e4>>5, k4 = (e4&31)*4;
    float4 v = __ldg(reinterpret_cast<const float4*>(wg + n*CDIM) + (e4&31));
    split_store4(dh, dl, (u32)(n*TP + k4)*2, v);
  }
}
// ---------------- mma.sync / ldmatrix --------------------------------------
__device__ __forceinline__ void ldmA(u32* r, u32 addr){
  asm volatile("ldmatrix.sync.aligned.m8n8.x4.shared.b16 {%0,%1,%2,%3}, [%4];"
    : "=r"(r[0]),"=r"(r[1]),"=r"(r[2]),"=r"(r[3]) : "r"(addr));
}
__device__ __forceinline__ void ldmB(u32* r, u32 addr){
  asm volatile("ldmatrix.sync.aligned.m8n8.x2.shared.b16 {%0,%1}, [%2];"
    : "=r"(r[0]),"=r"(r[1]) : "r"(addr));
}
__device__ __forceinline__ void ldmBt(u32* r, u32 addr){
  asm volatile("ldmatrix.sync.aligned.m8n8.x2.trans.shared.b16 {%0,%1}, [%2];"
    : "=r"(r[0]),"=r"(r[1]) : "r"(addr));
}
__device__ __forceinline__ void mma16816(float* c, const u32* a, const u32* b){
  asm volatile("mma.sync.aligned.m16n8k16.row.col.f32.bf16.bf16.f32 "
    "{%0,%1,%2,%3}, {%4,%5,%6,%7}, {%8,%9}, {%0,%1,%2,%3};"
    : "+f"(c[0]),"+f"(c[1]),"+f"(c[2]),"+f"(c[3])
    : "r"(a[0]),"r"(a[1]),"r"(a[2]),"r"(a[3]), "r"(b[0]),"r"(b[1]));
}
// 64x128x128 GEMM, 3-term split; warp (wm 0..3, wn 0..3) owns 16x32 of output
__device__ __forceinline__ void mma_gemm16(
    u32 aH, u32 aL, u32 bH, u32 bL,
    int wm, int wn, int lr, int lk, int br, int bk, float acc[4][4])
{
  #pragma unroll
  for (int k0 = 0; k0 < 128; k0 += 16){
    u32 ah[4], al[4], bh[4][2], bl[4][2];
    u32 ar = (u32)((wm*16 + lr)*TP + k0 + lk*8)*2;
    ldmA(ah, aH + ar);
    ldmA(al, aL + ar);
    #pragma unroll
    for (int nt = 0; nt < 4; ++nt){
      u32 brr = (u32)((wn*32 + nt*8 + br)*TP + k0 + bk*8)*2;
      ldmB(bh[nt], bH + brr);
      ldmB(bl[nt], bL + brr);
    }
    #pragma unroll
    for (int nt = 0; nt < 4; ++nt){
      mma16816(acc[nt], ah, bh[nt]);
      mma16816(acc[nt], ah, bl[nt]);
      mma16816(acc[nt], al, bh[nt]);
    }
  }
}
// attn finisher: add precomputed bias+mask from smem table, zero pad region
__device__ __forceinline__ float finv(int t, int s, float v, int h, const char* bm){
  if (t >= T49 || s >= T49) return 0.f;
  return v + *reinterpret_cast<const float*>(bm + (u32)(t*T49+s)*16 + h*4);
}

__global__ void __launch_bounds__(512, 1)
wattn_kernel(const float* __restrict__ x, const float* __restrict__ mask,
             const float* __restrict__ qkv_w, const float* __restrict__ qkv_b,
             const float* __restrict__ proj_w, const float* __restrict__ proj_b,
             const float* __restrict__ bias_table, float* __restrict__ out)
{
  extern __shared__ char smc[];
  const u32 sm0 = smem_u32(smc);

  const int b   = blockIdx.x;
  const int tid = threadIdx.x;
  const int tx  = tid & 31;
  const int w   = tid >> 5;                 // warp 0..15
  const int lr = tx & 15, lk = tx >> 4;     // A ldmatrix roles
  const int br = tx & 7,  bk = (tx >> 3) & 1;
  const int quad = tx >> 2, qc = tx & 3;    // D fragment roles
  const int wm = w & 3, wn = w >> 2;        // GEMM warp grid 4x4

  // ---- stage 1: x tiles; Wqkv ch0; bias+mask table ------------------------
  {
    const float4* xg = reinterpret_cast<const float4*>(x + (size_t)b*(T49*CDIM));
    #pragma unroll
    for (int it = 0; it < 4; ++it) {
      int e4 = tid + it*512;
      if (e4 < T49*32) {
        int r = e4 >> 5, c4 = (e4 & 31)*4;
        split_store4(smc+XH_OFF, smc+XL_OFF, (u32)(r*TP + c4)*2, __ldg(xg + e4));
      }
    }
    stage_w(smc+WH_OFF, smc+WL_OFF, qkv_w, tid);
    // bm[t][s][h] = bias_table[rel(t,s)][h] + mask[win][t][s]
    const float* mrow = mask + (size_t)(b & 63)*(T49*T49);
    for (int i = tid; i < T49*T49; i += 512) {
      int t = i / T49, s = i - t*T49;
      int th = t/7, tw = t - th*7, sh = s/7, sw = s - sh*7;
      int rel = (th - sh + 6)*13 + (tw - sw + 6);
      float4 bb = __ldg(reinterpret_cast<const float4*>(bias_table) + rel);
      float mk = __ldg(&mrow[i]);
      *reinterpret_cast<float4*>(smc + BM_OFF + (u32)i*16) =
          make_float4(bb.x+mk, bb.y+mk, bb.z+mk, bb.w+mk);
    }
  }
  __syncthreads();

  // ---- stage 2: QKV GEMM, epilogue splits straight into q/k/v tiles -------
  const float scale = 0.17677669529663687f;     // 32^-0.5 (folded into q)
  #pragma unroll 1
  for (int ch = 0; ch < 3; ++ch) {
    float acc[4][4];
    #pragma unroll
    for (int nt=0;nt<4;++nt)
      #pragma unroll
      for (int e=0;e<4;++e) acc[nt][e] = 0.f;

    mma_gemm16(sm0+XH_OFF, sm0+XL_OFF, sm0+WH_OFF, sm0+WL_OFF,
               wm, wn, lr, lk, br, bk, acc);
    if (ch == 2) __syncthreads();     // v overwrites x: all A reads must drain

    char* dh = smc + ((ch==0)?QH_OFF:(ch==1)?KH_OFF:XH_OFF);
    char* dl = smc + ((ch==0)?QL_OFF:(ch==1)?KL_OFF:XL_OFF);
    #pragma unroll
    for (int nt = 0; nt < 4; ++nt) {
      int c  = wn*32 + nt*8 + qc*2;
      float2 bb = __ldg(reinterpret_cast<const float2*>(qkv_b + ch*CDIM + c));
      int r1 = wm*16 + quad, r2 = r1 + 8;
      float v0 = (r1 < T49) ? acc[nt][0] + bb.x : 0.f;
      float v1 = (r1 < T49) ? acc[nt][1] + bb.y : 0.f;
      float v2 = (r2 < T49) ? acc[nt][2] + bb.x : 0.f;
      float v3 = (r2 < T49) ? acc[nt][3] + bb.y : 0.f;
      if (ch == 0) { v0*=scale; v1*=scale; v2*=scale; v3*=scale; }
      split_store2(dh, dl, (u32)(r1*TP + c)*2, v0, v1);
      split_store2(dh, dl, (u32)(r2*TP + c)*2, v2, v3);
    }
    __syncthreads();                  // epilogue writes done (and W reads done)
    if (ch < 2) {
      stage_w(smc+WH_OFF, smc+WL_OFF, qkv_w + (ch+1)*CDIM*CDIM, tid);
      __syncthreads();
    }
  }

  // ---- stage proj weights now (W region dead; overlaps nothing it shouldn't)
  stage_w(smc+WH_OFF, smc+WL_OFF, proj_w, tid);

  // ---- fused attention: attn = q.k^T + bm  -->  o2 = attn @ v, in-register -
  {
    const int h = w >> 2, rb = w & 3;       // 4 heads x 4 row-blocks of 16
    const int lr16 = tx & 15;
    const char* bm = smc + BM_OFF;

    float acc[8][4];
    #pragma unroll
    for (int nt=0;nt<8;++nt)
      #pragma unroll
      for (int e=0;e<4;++e) acc[nt][e] = 0.f;

    #pragma unroll
    for (int k0 = 0; k0 < 32; k0 += 16) {
      u32 qh_[4], ql_[4];
      u32 ar = (u32)((rb*16 + lr)*TP + h*32 + k0 + lk*8)*2;
      ldmA(qh_, sm0+QH_OFF + ar);
      ldmA(ql_, sm0+QL_OFF + ar);
      #pragma unroll
      for (int nt = 0; nt < 8; ++nt){
        u32 kh_[2], kl_[2];
        u32 brr = (u32)((nt*8 + br)*TP + h*32 + k0 + bk*8)*2;
        ldmB(kh_, sm0+KH_OFF + brr);
        ldmB(kl_, sm0+KL_OFF + brr);
        mma16816(acc[nt], qh_, kh_);
        mma16816(acc[nt], qh_, kl_);
        mma16816(acc[nt], ql_, kh_);
      }
    }

    const int r1 = rb*16 + quad, r2 = r1 + 8;
    float o2[4][4];
    #pragma unroll
    for (int nt=0;nt<4;++nt)
      #pragma unroll
      for (int e=0;e<4;++e) o2[nt][e] = 0.f;

    // D->A fragment conversion per k16 slab sf, immediately consumed by attn@v
    #pragma unroll
    for (int sf = 0; sf < 4; ++sf) {
      int sA = sf*16 + 2*qc, sB = sA + 8;
      float v00 = finv(r1, sA,   acc[2*sf  ][0], h, bm);
      float v01 = finv(r1, sA+1, acc[2*sf  ][1], h, bm);
      float v10 = finv(r2, sA,   acc[2*sf  ][2], h, bm);
      float v11 = finv(r2, sA+1, acc[2*sf  ][3], h, bm);
      float w00 = finv(r1, sB,   acc[2*sf+1][0], h, bm);
      float w01 = finv(r1, sB+1, acc[2*sf+1][1], h, bm);
      float w10 = finv(r2, sB,   acc[2*sf+1][2], h, bm);
      float w11 = finv(r2, sB+1, acc[2*sf+1][3], h, bm);
      u32 ah_[4], al_[4];
      pksplit(v00, v01, ah_[0], al_[0]);   // a0: row r1, k 0-7 slot
      pksplit(v10, v11, ah_[1], al_[1]);   // a1: row r2
      pksplit(w00, w01, ah_[2], al_[2]);   // a2: row r1, k 8-15 slot
      pksplit(w10, w11, ah_[3], al_[3]);   // a3: row r2
      #pragma unroll
      for (int nt2 = 0; nt2 < 4; ++nt2) {
        u32 vh_[2], vl_[2];
        u32 brr = (u32)((sf*16 + lr16)*TP + h*32 + nt2*8)*2;
        ldmBt(vh_, sm0+XH_OFF + brr);      // v aliased over x
        ldmBt(vl_, sm0+XL_OFF + brr);
        mma16816(o2[nt2], ah_, vh_);
        mma16816(o2[nt2], ah_, vl_);
        mma16816(o2[nt2], al_, vh_);
      }
    }
    __syncthreads();                       // q/k/v reads + proj staging drain
    #pragma unroll
    for (int nt2 = 0; nt2 < 4; ++nt2) {
      int c = h*32 + nt2*8 + 2*qc;
      split_store2(smc+QH_OFF, smc+QL_OFF, (u32)(r1*TP + c)*2,
                   o2[nt2][0], o2[nt2][1]);
      split_store2(smc+QH_OFF, smc+QL_OFF, (u32)(r2*TP + c)*2,
                   o2[nt2][2], o2[nt2][3]);
    }
  }
  __syncthreads();

  // ---- stage 4: out = o2 @ proj_w^T + b via HMMA --------------------------
  {
    float acc[4][4];
    #pragma unroll
    for (int nt=0;nt<4;++nt)
      #pragma unroll
      for (int e=0;e<4;++e) acc[nt][e] = 0.f;

    mma_gemm16(sm0+QH_OFF, sm0+QL_OFF, sm0+WH_OFF, sm0+WL_OFF,
               wm, wn, lr, lk, br, bk, acc);

    float* o_s = reinterpret_cast<float*>(smc + OS_OFF);   // k tiles dead
    #pragma unroll
    for (int nt = 0; nt < 4; ++nt) {
      int c  = wn*32 + nt*8 + qc*2;
      float2 bb = __ldg(reinterpret_cast<const float2*>(proj_b + c));
      int r1 = wm*16 + quad, r2 = r1 + 8;
      if (r1 < T49)
        *reinterpret_cast<float2*>(&o_s[r1*OP + c]) =
            make_float2(acc[nt][0]+bb.x, acc[nt][1]+bb.y);
      if (r2 < T49)
        *reinterpret_cast<float2*>(&o_s[r2*OP + c]) =
            make_float2(acc[nt][2]+bb.x, acc[nt][3]+bb.y);
    }
  }
  __syncthreads();

  // ---- coalesced store ----------------------------------------------------
  {
    const float* o_s = reinterpret_cast<const float*>(smc + OS_OFF);
    float4* og = reinterpret_cast<float4*>(out + (size_t)b*(T49*CDIM));
    #pragma unroll
    for (int it = 0; it < 4; ++it) {
      int e4 = tid + it*512;
      if (e4 < T49*32) {
        int r = e4 >> 5, c4 = (e4 & 31)*4;
        og[e4] = *reinterpret_cast<const float4*>(&o_s[r*OP + c4]);
      }
    }
  }
}

extern "C" void kernel_launch(void* const* d_in, const int* in_sizes, int n_in,
                              void* d_out, int out_size)
{
  const float* x      = (const float*)d_in[0];
  const float* mask   = (const float*)d_in[1];
  const float* qkv_w  = (const float*)d_in[2];
  const float* qkv_b  = (const float*)d_in[3];
  const float* proj_w = (const float*)d_in[4];
  const float* proj_b = (const float*)d_in[5];
  const float* btab   = (const float*)d_in[6];
  float* out = (float*)d_out;

  int B = in_sizes[0] / (T49*CDIM);   // 8192 windows

  cudaFuncSetAttribute(wattn_kernel,
                       cudaFuncAttributeMaxDynamicSharedMemorySize, SMEM_BYTES);
  wattn_kernel<<<B, 512, SMEM_BYTES>>>(x, mask, qkv_w, qkv_b,
                                       proj_w, proj_b, btab, out);
}

// round 13
// speedup vs baseline: 2.1008x; 1.0760x over previous
#include <cuda_runtime.h>
#include <cuda_fp16.h>

typedef unsigned long long u64;
typedef unsigned int u32;

#define T49   49
#define CDIM  128
#define NH    4
#define TP    136      /* fp16 tile pitch in elements (272B/row) */
#define OP    132      /* o_s fp32 pitch */

/* byte offsets; aliases noted */
#define X_OFF   0                  /* x single fp16 ; VH alias        */
#define VH_OFF  0
#define VL_OFF  17408
#define QH_OFF  34816              /* q hi/lo -> o2 hi/lo (after attn)*/
#define QL_OFF  52224
#define KH_OFF  69632
#define KL_OFF  87040
#define WH_OFF  104448             /* W hi/lo fp16                    */
#define WL_OFF  139264
#define BM_OFF  174080             /* bias+mask [49][49][4] f32; o_s alias */
#define OS_OFF  174080
#define SMEM_BYTES 212496

// ---------------- helpers --------------------------------------------------
__device__ __forceinline__ u32 smem_u32(const void* p){
  u32 a; asm("{ .reg .u64 t; cvta.to.shared.u64 t, %1; cvt.u32.u64 %0, t; }"
             : "=r"(a) : "l"(p));
  return a;
}
__device__ __forceinline__ u32 pkh(float lo, float hi){   // low half = lo
  u32 r; asm("cvt.rn.f16x2.f32 %0, %1, %2;" : "=r"(r) : "f"(hi), "f"(lo));
  return r;
}
__device__ __forceinline__ void pksplit(float a, float b, u32 &hw, u32 &lw){
  __half ha=__float2half_rn(a), hb=__float2half_rn(b);
  hw = (u32)__half_as_ushort(ha) | ((u32)__half_as_ushort(hb)<<16);
  lw = (u32)__half_as_ushort(__float2half_rn(a-__half2float(ha)))
     | ((u32)__half_as_ushort(__float2half_rn(b-__half2float(hb)))<<16);
}
__device__ __forceinline__ void split_store2(char* th_, char* tl_, u32 off,
                                             float a, float b){
  u32 hw, lw; pksplit(a, b, hw, lw);
  *reinterpret_cast<u32*>(th_+off) = hw;
  *reinterpret_cast<u32*>(tl_+off) = lw;
}
// stage 128x128 fp32 weight block (row = out-channel n, col = k), hi/lo fp16
__device__ __forceinline__ void stage_w(char* dh, char* dl, const float* wg, int tid){
  #pragma unroll
  for (int it = 0; it < 16; ++it){
    int e4 = tid + it*256;
    int n = e4>>5, k4 = (e4&31)*4;
    float4 v = __ldg(reinterpret_cast<const float4*>(wg + n*CDIM) + (e4&31));
    u32 h01, l01, h23, l23;
    pksplit(v.x, v.y, h01, l01);
    pksplit(v.z, v.w, h23, l23);
    u32 off = (u32)(n*TP + k4)*2;
    *reinterpret_cast<u64*>(dh+off) = (u64)h01 | ((u64)h23<<32);
    *reinterpret_cast<u64*>(dl+off) = (u64)l01 | ((u64)l23<<32);
  }
}
// ---------------- mma.sync / ldmatrix --------------------------------------
__device__ __forceinline__ void ldmA(u32* r, u32 addr){
  asm volatile("ldmatrix.sync.aligned.m8n8.x4.shared.b16 {%0,%1,%2,%3}, [%4];"
    : "=r"(r[0]),"=r"(r[1]),"=r"(r[2]),"=r"(r[3]) : "r"(addr));
}
__device__ __forceinline__ void ldmB(u32* r, u32 addr){
  asm volatile("ldmatrix.sync.aligned.m8n8.x2.shared.b16 {%0,%1}, [%2];"
    : "=r"(r[0]),"=r"(r[1]) : "r"(addr));
}
__device__ __forceinline__ void ldmBt(u32* r, u32 addr){
  asm volatile("ldmatrix.sync.aligned.m8n8.x2.trans.shared.b16 {%0,%1}, [%2];"
    : "=r"(r[0]),"=r"(r[1]) : "r"(addr));
}
__device__ __forceinline__ void mma16816(float* c, const u32* a, const u32* b){
  asm volatile("mma.sync.aligned.m16n8k16.row.col.f32.f16.f16.f32 "
    "{%0,%1,%2,%3}, {%4,%5,%6,%7}, {%8,%9}, {%0,%1,%2,%3};"
    : "+f"(c[0]),"+f"(c[1]),"+f"(c[2]),"+f"(c[3])
    : "r"(a[0]),"r"(a[1]),"r"(a[2]),"r"(a[3]), "r"(b[0]),"r"(b[1]));
}
// 64x128x128 GEMM, A single fp16, W hi/lo (2 terms); warp tile 32x32, grid 2x4
__device__ __forceinline__ void mma_gemm_a1(
    u32 aS, u32 bH, u32 bL,
    int wm, int wn, int lr, int lk, int br, int bk, float acc[2][4][4])
{
  #pragma unroll
  for (int k0 = 0; k0 < 128; k0 += 16){
    u32 a_[2][4], bh_[4][2], bl_[4][2];
    #pragma unroll
    for (int mt = 0; mt < 2; ++mt)
      ldmA(a_[mt], aS + (u32)((wm*32 + mt*16 + lr)*TP + k0 + lk*8)*2);
    #pragma unroll
    for (int nt = 0; nt < 4; ++nt){
      u32 brr = (u32)((wn*32 + nt*8 + br)*TP + k0 + bk*8)*2;
      ldmB(bh_[nt], bH + brr);
      ldmB(bl_[nt], bL + brr);
    }
    #pragma unroll
    for (int mt = 0; mt < 2; ++mt)
      #pragma unroll
      for (int nt = 0; nt < 4; ++nt){
        mma16816(acc[mt][nt], a_[mt], bh_[nt]);
        mma16816(acc[mt][nt], a_[mt], bl_[nt]);
      }
  }
}
// A hi/lo, W hi/lo (3 terms) — for proj
__device__ __forceinline__ void mma_gemm_a2(
    u32 aH, u32 aL, u32 bH, u32 bL,
    int wm, int wn, int lr, int lk, int br, int bk, float acc[2][4][4])
{
  #pragma unroll
  for (int k0 = 0; k0 < 128; k0 += 16){
    u32 ah[2][4], al[2][4], bh_[4][2], bl_[4][2];
    #pragma unroll
    for (int mt = 0; mt < 2; ++mt){
      u32 ar = (u32)((wm*32 + mt*16 + lr)*TP + k0 + lk*8)*2;
      ldmA(ah[mt], aH + ar);
      ldmA(al[mt], aL + ar);
    }
    #pragma unroll
    for (int nt = 0; nt < 4; ++nt){
      u32 brr = (u32)((wn*32 + nt*8 + br)*TP + k0 + bk*8)*2;
      ldmB(bh_[nt], bH + brr);
      ldmB(bl_[nt], bL + brr);
    }
    #pragma unroll
    for (int mt = 0; mt < 2; ++mt)
      #pragma unroll
      for (int nt = 0; nt < 4; ++nt){
        mma16816(acc[mt][nt], ah[mt], bh_[nt]);
        mma16816(acc[mt][nt], ah[mt], bl_[nt]);
        mma16816(acc[mt][nt], al[mt], bh_[nt]);
      }
  }
}
__device__ __forceinline__ float finv(int t, int s, float v, int h, const char* bm){
  if (t >= T49 || s >= T49) return 0.f;
  return v + *reinterpret_cast<const float*>(bm + (u32)(t*T49+s)*16 + h*4);
}

__global__ void __launch_bounds__(256, 1)
wattn_kernel(const float* __restrict__ x, const float* __restrict__ mask,
             const float* __restrict__ qkv_w, const float* __restrict__ qkv_b,
             const float* __restrict__ proj_w, const float* __restrict__ proj_b,
             const float* __restrict__ bias_table, float* __restrict__ out)
{
  extern __shared__ char smc[];
  const u32 sm0 = smem_u32(smc);

  const int b   = blockIdx.x;
  const int tid = threadIdx.x;
  const int tx  = tid & 31;
  const int w   = tid >> 5;                 // warp 0..7
  const int lr = tx & 15, lk = tx >> 4;     // A ldmatrix roles
  const int br = tx & 7,  bk = (tx >> 3) & 1;
  const int quad = tx >> 2, qc = tx & 3;    // D fragment roles
  const int wm = w & 1, wn = w >> 1;        // GEMM warp grid 2x4, tile 32x32

  // ---- stage 1: x (single fp16); Wqkv ch0; bias+mask table ----------------
  {
    const float4* xg = reinterpret_cast<const float4*>(x + (size_t)b*(T49*CDIM));
    #pragma unroll
    for (int it = 0; it < 7; ++it) {
      int e4 = tid + it*256;
      if (e4 < T49*32) {
        int r = e4 >> 5, c4 = (e4 & 31)*4;
        float4 v = __ldg(xg + e4);
        *reinterpret_cast<u64*>(smc + X_OFF + (u32)(r*TP + c4)*2) =
            (u64)pkh(v.x, v.y) | ((u64)pkh(v.z, v.w)<<32);
      }
    }
    stage_w(smc+WH_OFF, smc+WL_OFF, qkv_w, tid);
    const float* mrow = mask + (size_t)(b & 63)*(T49*T49);
    for (int i = tid; i < T49*T49; i += 256) {
      int t = i / T49, s = i - t*T49;
      int th = t/7, tw = t - th*7, sh = s/7, sw = s - sh*7;
      int rel = (th - sh + 6)*13 + (tw - sw + 6);
      float4 bb = __ldg(reinterpret_cast<const float4*>(bias_table) + rel);
      float mk = __ldg(&mrow[i]);
      *reinterpret_cast<float4*>(smc + BM_OFF + (u32)i*16) =
          make_float4(bb.x+mk, bb.y+mk, bb.z+mk, bb.w+mk);
    }
  }
  __syncthreads();

  // ---- stage 2: QKV GEMM (A=x single, 2-term), epilogue -> q/k/v hi/lo ----
  const float scale = 0.17677669529663687f;     // 32^-0.5 (folded into q)
  #pragma unroll 1
  for (int ch = 0; ch < 3; ++ch) {
    float acc[2][4][4];
    #pragma unroll
    for (int mt=0;mt<2;++mt)
      #pragma unroll
      for (int nt=0;nt<4;++nt)
        #pragma unroll
        for (int e=0;e<4;++e) acc[mt][nt][e] = 0.f;

    mma_gemm_a1(sm0+X_OFF, sm0+WH_OFF, sm0+WL_OFF,
                wm, wn, lr, lk, br, bk, acc);
    if (ch == 2) __syncthreads();     // v overwrites x: all A reads must drain

    char* dh = smc + ((ch==0)?QH_OFF:(ch==1)?KH_OFF:VH_OFF);
    char* dl = smc + ((ch==0)?QL_OFF:(ch==1)?KL_OFF:VL_OFF);
    #pragma unroll
    for (int mt = 0; mt < 2; ++mt)
      #pragma unroll
      for (int nt = 0; nt < 4; ++nt) {
        int c  = wn*32 + nt*8 + qc*2;
        float2 bb = __ldg(reinterpret_cast<const float2*>(qkv_b + ch*CDIM + c));
        int r1 = wm*32 + mt*16 + quad, r2 = r1 + 8;
        float v0 = (r1 < T49) ? acc[mt][nt][0] + bb.x : 0.f;
        float v1 = (r1 < T49) ? acc[mt][nt][1] + bb.y : 0.f;
        float v2 = (r2 < T49) ? acc[mt][nt][2] + bb.x : 0.f;
        float v3 = (r2 < T49) ? acc[mt][nt][3] + bb.y : 0.f;
        if (ch == 0) { v0*=scale; v1*=scale; v2*=scale; v3*=scale; }
        split_store2(dh, dl, (u32)(r1*TP + c)*2, v0, v1);
        split_store2(dh, dl, (u32)(r2*TP + c)*2, v2, v3);
      }
    __syncthreads();
    if (ch < 2) {
      stage_w(smc+WH_OFF, smc+WL_OFF, qkv_w + (ch+1)*CDIM*CDIM, tid);
      __syncthreads();
    }
  }

  // ---- stage proj weights (W region dead; attention doesn't touch W) ------
  stage_w(smc+WH_OFF, smc+WL_OFF, proj_w, tid);

  // ---- fused attention: attn = q.k^T + bm --> o2 = attn @ v, 3-term fp16 --
  {
    const int h = w >> 1, rb = w & 1;       // 4 heads x 2 row-blocks of 32
    const int lr16 = tx & 15;
    const char* bm = smc + BM_OFF;

    float accA[2][8][4];
    #pragma unroll
    for (int mt=0;mt<2;++mt)
      #pragma unroll
      for (int nt=0;nt<8;++nt)
        #pragma unroll
        for (int e=0;e<4;++e) accA[mt][nt][e] = 0.f;

    #pragma unroll
    for (int k0 = 0; k0 < 32; k0 += 16) {
      u32 qh_[2][4], ql_[2][4];
      #pragma unroll
      for (int mt = 0; mt < 2; ++mt){
        u32 ar = (u32)((rb*32 + mt*16 + lr)*TP + h*32 + k0 + lk*8)*2;
        ldmA(qh_[mt], sm0+QH_OFF + ar);
        ldmA(ql_[mt], sm0+QL_OFF + ar);
      }
      #pragma unroll
      for (int nt = 0; nt < 8; ++nt){
        u32 kh_[2], kl_[2];
        u32 brr = (u32)((nt*8 + br)*TP + h*32 + k0 + bk*8)*2;
        ldmB(kh_, sm0+KH_OFF + brr);
        ldmB(kl_, sm0+KL_OFF + brr);
        #pragma unroll
        for (int mt = 0; mt < 2; ++mt){
          mma16816(accA[mt][nt], qh_[mt], kh_);
          mma16816(accA[mt][nt], qh_[mt], kl_);
          mma16816(accA[mt][nt], ql_[mt], kh_);
        }
      }
    }

    float o2[2][4][4];
    #pragma unroll
    for (int mt=0;mt<2;++mt)
      #pragma unroll
      for (int nt=0;nt<4;++nt)
        #pragma unroll
        for (int e=0;e<4;++e) o2[mt][nt][e] = 0.f;

    #pragma unroll
    for (int sf = 0; sf < 4; ++sf) {
      u32 vh_[4][2], vl_[4][2];
      #pragma unroll
      for (int nt2 = 0; nt2 < 4; ++nt2){
        u32 brr = (u32)((sf*16 + lr16)*TP + h*32 + nt2*8)*2;
        ldmBt(vh_[nt2], sm0+VH_OFF + brr);
        ldmBt(vl_[nt2], sm0+VL_OFF + brr);
      }
      #pragma unroll
      for (int mt = 0; mt < 2; ++mt) {
        int r1 = rb*32 + mt*16 + quad, r2 = r1 + 8;
        int sA = sf*16 + 2*qc, sB = sA + 8;
        float v00 = finv(r1, sA,   accA[mt][2*sf  ][0], h, bm);
        float v01 = finv(r1, sA+1, accA[mt][2*sf  ][1], h, bm);
        float v10 = finv(r2, sA,   accA[mt][2*sf  ][2], h, bm);
        float v11 = finv(r2, sA+1, accA[mt][2*sf  ][3], h, bm);
        float w00 = finv(r1, sB,   accA[mt][2*sf+1][0], h, bm);
        float w01 = finv(r1, sB+1, accA[mt][2*sf+1][1], h, bm);
        float w10 = finv(r2, sB,   accA[mt][2*sf+1][2], h, bm);
        float w11 = finv(r2, sB+1, accA[mt][2*sf+1][3], h, bm);
        u32 ah_[4], al_[4];
        pksplit(v00, v01, ah_[0], al_[0]);
        pksplit(v10, v11, ah_[1], al_[1]);
        pksplit(w00, w01, ah_[2], al_[2]);
        pksplit(w10, w11, ah_[3], al_[3]);
        #pragma unroll
        for (int nt2 = 0; nt2 < 4; ++nt2) {
          mma16816(o2[mt][nt2], ah_, vh_[nt2]);
          mma16816(o2[mt][nt2], ah_, vl_[nt2]);
          mma16816(o2[mt][nt2], al_, vh_[nt2]);
        }
      }
    }
    // o2 -> q region (own rows/cols only; in-warp reads already complete)
    #pragma unroll
    for (int mt = 0; mt < 2; ++mt) {
      int r1 = rb*32 + mt*16 + quad, r2 = r1 + 8;
      #pragma unroll
      for (int nt2 = 0; nt2 < 4; ++nt2) {
        int c = h*32 + nt2*8 + 2*qc;
        split_store2(smc+QH_OFF, smc+QL_OFF, (u32)(r1*TP + c)*2,
                     o2[mt][nt2][0], o2[mt][nt2][1]);
        split_store2(smc+QH_OFF, smc+QL_OFF, (u32)(r2*TP + c)*2,
                     o2[mt][nt2][2], o2[mt][nt2][3]);
      }
    }
  }
  __syncthreads();

  // ---- stage 4: out = o2 @ proj_w^T + b (A hi/lo, 3-term) -----------------
  {
    float acc[2][4][4];
    #pragma unroll
    for (int mt=0;mt<2;++mt)
      #pragma unroll
      for (int nt=0;nt<4;++nt)
        #pragma unroll
        for (int e=0;e<4;++e) acc[mt][nt][e] = 0.f;

    mma_gemm_a2(sm0+QH_OFF, sm0+QL_OFF, sm0+WH_OFF, sm0+WL_OFF,
                wm, wn, lr, lk, br, bk, acc);

    float* o_s = reinterpret_cast<float*>(smc + OS_OFF);   // BM region dead
    #pragma unroll
    for (int mt = 0; mt < 2; ++mt)
      #pragma unroll
      for (int nt = 0; nt < 4; ++nt) {
        int c  = wn*32 + nt*8 + qc*2;
        float2 bb = __ldg(reinterpret_cast<const float2*>(proj_b + c));
        int r1 = wm*32 + mt*16 + quad, r2 = r1 + 8;
        if (r1 < T49)
          *reinterpret_cast<float2*>(&o_s[r1*OP + c]) =
              make_float2(acc[mt][nt][0]+bb.x, acc[mt][nt][1]+bb.y);
        if (r2 < T49)
          *reinterpret_cast<float2*>(&o_s[r2*OP + c]) =
              make_float2(acc[mt][nt][2]+bb.x, acc[mt][nt][3]+bb.y);
      }
  }
  __syncthreads();

  // ---- coalesced store ----------------------------------------------------
  {
    const float* o_s = reinterpret_cast<const float*>(smc + OS_OFF);
    float4* og = reinterpret_cast<float4*>(out + (size_t)b*(T49*CDIM));
    #pragma unroll
    for (int it = 0; it < 7; ++it) {
      int e4 = tid + it*256;
      if (e4 < T49*32) {
        int r = e4 >> 5, c4 = (e4 & 31)*4;
        og[e4] = *reinterpret_cast<const float4*>(&o_s[r*OP + c4]);
      }
    }
  }
}

extern "C" void kernel_launch(void* const* d_in, const int* in_sizes, int n_in,
                              void* d_out, int out_size)
{
  const float* x      = (const float*)d_in[0];
  const float* mask   = (const float*)d_in[1];
  const float* qkv_w  = (const float*)d_in[2];
  const float* qkv_b  = (const float*)d_in[3];
  const float* proj_w = (const float*)d_in[4];
  const float* proj_b = (const float*)d_in[5];
  const float* btab   = (const float*)d_in[6];
  float* out = (float*)d_out;

  int B = in_sizes[0] / (T49*CDIM);   // 8192 windows

  cudaFuncSetAttribute(wattn_kernel,
                       cudaFuncAttributeMaxDynamicSharedMemorySize, SMEM_BYTES);
  wattn_kernel<<<B, 256, SMEM_BYTES>>>(x, mask, qkv_w, qkv_b,
                                       proj_w, proj_b, btab, out);
}

// round 15
// speedup vs baseline: 4.0552x; 1.9303x over previous
#include <cuda_runtime.h>
#include <cuda_fp16.h>

typedef unsigned long long u64;
typedef unsigned int u32;

#define T49   49
#define CDIM  128
#define NH    4
#define TP    136      /* fp16 tile pitch in elements (272B/row) */
#define OP    132      /* o_s fp32 pitch */

/* byte offsets (all fp16 tiles are 64x136 = 17408B unless noted) */
#define X_OFF   0                  /* x single fp16 ; v single alias      */
#define QH_OFF  17408              /* q hi -> o2 hi (in-place, slab-wise) */
#define QL_OFF  34816              /* q lo -> o2 lo                       */
#define K_OFF   52224              /* k single fp16                       */
#define W_OFF   69632              /* W single fp16, 128x136 = 34816      */
#define OS_OFF  17408              /* o_s fp32 aliases QH/QL after proj   */
#define SMEM_BYTES 104448          /* 2 CTAs/SM                           */

// ---------------- helpers --------------------------------------------------
__device__ __forceinline__ u32 smem_u32(const void* p){
  u32 a; asm("{ .reg .u64 t; cvta.to.shared.u64 t, %1; cvt.u32.u64 %0, t; }"
             : "=r"(a) : "l"(p));
  return a;
}
__device__ __forceinline__ u32 pkh(float lo, float hi){   // low half = lo
  u32 r; asm("cvt.rn.f16x2.f32 %0, %1, %2;" : "=r"(r) : "f"(hi), "f"(lo));
  return r;
}
__device__ __forceinline__ void pksplit(float a, float b, u32 &hw, u32 &lw){
  __half ha=__float2half_rn(a), hb=__float2half_rn(b);
  hw = (u32)__half_as_ushort(ha) | ((u32)__half_as_ushort(hb)<<16);
  lw = (u32)__half_as_ushort(__float2half_rn(a-__half2float(ha)))
     | ((u32)__half_as_ushort(__float2half_rn(b-__half2float(hb)))<<16);
}
__device__ __forceinline__ void split_store2(char* th_, char* tl_, u32 off,
                                             float a, float b){
  u32 hw, lw; pksplit(a, b, hw, lw);
  *reinterpret_cast<u32*>(th_+off) = hw;
  *reinterpret_cast<u32*>(tl_+off) = lw;
}
// stage 128x128 fp32 weight block (row = out-channel n, col = k), single fp16
__device__ __forceinline__ void stage_w(char* dw, const float* wg, int tid){
  #pragma unroll
  for (int it = 0; it < 16; ++it){
    int e4 = tid + it*256;
    int n = e4>>5, k4 = (e4&31)*4;
    float4 v = __ldg(reinterpret_cast<const float4*>(wg + n*CDIM) + (e4&31));
    *reinterpret_cast<u64*>(dw + (u32)(n*TP + k4)*2) =
        (u64)pkh(v.x, v.y) | ((u64)pkh(v.z, v.w)<<32);
  }
}
// ---------------- mma.sync / ldmatrix --------------------------------------
__device__ __forceinline__ void ldmA(u32* r, u32 addr){
  asm volatile("ldmatrix.sync.aligned.m8n8.x4.shared.b16 {%0,%1,%2,%3}, [%4];"
    : "=r"(r[0]),"=r"(r[1]),"=r"(r[2]),"=r"(r[3]) : "r"(addr));
}
__device__ __forceinline__ void ldmB(u32* r, u32 addr){
  asm volatile("ldmatrix.sync.aligned.m8n8.x2.shared.b16 {%0,%1}, [%2];"
    : "=r"(r[0]),"=r"(r[1]) : "r"(addr));
}
__device__ __forceinline__ void ldmBt(u32* r, u32 addr){
  asm volatile("ldmatrix.sync.aligned.m8n8.x2.trans.shared.b16 {%0,%1}, [%2];"
    : "=r"(r[0]),"=r"(r[1]) : "r"(addr));
}
__device__ __forceinline__ void mma16816(float* c, const u32* a, const u32* b){
  asm volatile("mma.sync.aligned.m16n8k16.row.col.f32.f16.f16.f32 "
    "{%0,%1,%2,%3}, {%4,%5,%6,%7}, {%8,%9}, {%0,%1,%2,%3};"
    : "+f"(c[0]),"+f"(c[1]),"+f"(c[2]),"+f"(c[3])
    : "r"(a[0]),"r"(a[1]),"r"(a[2]),"r"(a[3]), "r"(b[0]),"r"(b[1]));
}
// 64x128x128 GEMM, A single, B single (1 term); warp tile 32x32, grid 2x4
__device__ __forceinline__ void mma_gemm_ss(
    u32 aS, u32 bS, int wm, int wn, int lr, int lk, int br, int bk,
    float acc[2][4][4])
{
  #pragma unroll
  for (int k0 = 0; k0 < 128; k0 += 16){
    u32 a_[2][4], b_[4][2];
    #pragma unroll
    for (int mt = 0; mt < 2; ++mt)
      ldmA(a_[mt], aS + (u32)((wm*32 + mt*16 + lr)*TP + k0 + lk*8)*2);
    #pragma unroll
    for (int nt = 0; nt < 4; ++nt)
      ldmB(b_[nt], bS + (u32)((wn*32 + nt*8 + br)*TP + k0 + bk*8)*2);
    #pragma unroll
    for (int mt = 0; mt < 2; ++mt)
      #pragma unroll
      for (int nt = 0; nt < 4; ++nt)
        mma16816(acc[mt][nt], a_[mt], b_[nt]);
  }
}
// A hi/lo, B single (2 terms) — proj
__device__ __forceinline__ void mma_gemm_hl(
    u32 aH, u32 aL, u32 bS, int wm, int wn, int lr, int lk, int br, int bk,
    float acc[2][4][4])
{
  #pragma unroll
  for (int k0 = 0; k0 < 128; k0 += 16){
    u32 ah[2][4], al[2][4], b_[4][2];
    #pragma unroll
    for (int mt = 0; mt < 2; ++mt){
      u32 ar = (u32)((wm*32 + mt*16 + lr)*TP + k0 + lk*8)*2;
      ldmA(ah[mt], aH + ar);
      ldmA(al[mt], aL + ar);
    }
    #pragma unroll
    for (int nt = 0; nt < 4; ++nt)
      ldmB(b_[nt], bS + (u32)((wn*32 + nt*8 + br)*TP + k0 + bk*8)*2);
    #pragma unroll
    for (int mt = 0; mt < 2; ++mt)
      #pragma unroll
      for (int nt = 0; nt < 4; ++nt){
        mma16816(acc[mt][nt], ah[mt], b_[nt]);
        mma16816(acc[mt][nt], al[mt], b_[nt]);
      }
  }
}
// attn finisher: bias (L1-resident table) + mask (L2-resident), zero pad
__device__ __forceinline__ float fin(int t, int s, float v, int h,
    const float* __restrict__ bt, const float* __restrict__ mrow){
  if (t >= T49 || s >= T49) return 0.f;
  int th = t/7, tw = t - th*7, sh = s/7, sw = s - sh*7;
  int rel = (th - sh + 6)*13 + (tw - sw + 6);
  return v + __ldg(&bt[rel*NH + h]) + __ldg(&mrow[t*T49 + s]);
}

__global__ void __launch_bounds__(256, 2)
wattn_kernel(const float* __restrict__ x, const float* __restrict__ mask,
             const float* __restrict__ qkv_w, const float* __restrict__ qkv_b,
             const float* __restrict__ proj_w, const float* __restrict__ proj_b,
             const float* __restrict__ bias_table, float* __restrict__ out)
{
  extern __shared__ char smc[];
  const u32 sm0 = smem_u32(smc);

  const int b   = blockIdx.x;
  const int tid = threadIdx.x;
  const int tx  = tid & 31;
  const int w   = tid >> 5;                 // warp 0..7
  const int lr = tx & 15, lk = tx >> 4;     // A ldmatrix roles
  const int br = tx & 7,  bk = (tx >> 3) & 1;
  const int quad = tx >> 2, qc = tx & 3;    // D fragment roles
  const int wm = w & 1, wn = w >> 1;        // GEMM warp grid 2x4, tile 32x32

  // ---- stage 1: x (single fp16); Wqkv ch0 ---------------------------------
  {
    const float4* xg = reinterpret_cast<const float4*>(x + (size_t)b*(T49*CDIM));
    #pragma unroll
    for (int it = 0; it < 7; ++it) {
      int e4 = tid + it*256;
      if (e4 < T49*32) {
        int r = e4 >> 5, c4 = (e4 & 31)*4;
        float4 v = __ldg(xg + e4);
        *reinterpret_cast<u64*>(smc + X_OFF + (u32)(r*TP + c4)*2) =
            (u64)pkh(v.x, v.y) | ((u64)pkh(v.z, v.w)<<32);
      }
    }
    stage_w(smc+W_OFF, qkv_w, tid);
  }
  __syncthreads();

  // ---- stage 2: QKV GEMM (1-term), epilogue -> q hi/lo, k single, v single
  const float scale = 0.17677669529663687f;     // 32^-0.5 (folded into q)
  #pragma unroll 1
  for (int ch = 0; ch < 3; ++ch) {
    float acc[2][4][4];
    #pragma unroll
    for (int mt=0;mt<2;++mt)
      #pragma unroll
      for (int nt=0;nt<4;++nt)
        #pragma unroll
        for (int e=0;e<4;++e) acc[mt][nt][e] = 0.f;

    mma_gemm_ss(sm0+X_OFF, sm0+W_OFF, wm, wn, lr, lk, br, bk, acc);
    if (ch == 2) __syncthreads();     // v overwrites x: all A reads must drain

    #pragma unroll
    for (int mt = 0; mt < 2; ++mt)
      #pragma unroll
      for (int nt = 0; nt < 4; ++nt) {
        int c  = wn*32 + nt*8 + qc*2;
        float2 bb = __ldg(reinterpret_cast<const float2*>(qkv_b + ch*CDIM + c));
        int r1 = wm*32 + mt*16 + quad, r2 = r1 + 8;
        float v0 = (r1 < T49) ? acc[mt][nt][0] + bb.x : 0.f;
        float v1 = (r1 < T49) ? acc[mt][nt][1] + bb.y : 0.f;
        float v2 = (r2 < T49) ? acc[mt][nt][2] + bb.x : 0.f;
        float v3 = (r2 < T49) ? acc[mt][nt][3] + bb.y : 0.f;
        if (ch == 0) {                       // q: hi/lo split, scaled
          split_store2(smc+QH_OFF, smc+QL_OFF, (u32)(r1*TP + c)*2,
                       v0*scale, v1*scale);
          split_store2(smc+QH_OFF, smc+QL_OFF, (u32)(r2*TP + c)*2,
                       v2*scale, v3*scale);
        } else {                             // k / v: single fp16
          char* dst = smc + ((ch==1) ? K_OFF : X_OFF);
          *reinterpret_cast<u32*>(dst + (u32)(r1*TP + c)*2) = pkh(v0, v1);
          *reinterpret_cast<u32*>(dst + (u32)(r2*TP + c)*2) = pkh(v2, v3);
        }
      }
    __syncthreads();
    if (ch < 2) {
      stage_w(smc+W_OFF, qkv_w + (ch+1)*CDIM*CDIM, tid);
      __syncthreads();
    }
  }

  // ---- stage proj weights (W region dead; attention doesn't touch W) ------
  stage_w(smc+W_OFF, proj_w, tid);

  // ---- fused attention: slab-wise (16 rows) to fit the 128-reg cap --------
  // attn = q.k^T + bias + mask  -->  o2 = attn @ v ; o2 overwrites own q slab
  {
    const int h = w >> 1, rb = w & 1;       // 4 heads x 2 row-blocks of 32
    const int lr16 = tx & 15;
    const float* mrow = mask + (size_t)(b & 63)*(T49*T49);

    #pragma unroll 1
    for (int mt = 0; mt < 2; ++mt) {
      float accA[8][4];
      #pragma unroll
      for (int nt=0;nt<8;++nt)
        #pragma unroll
        for (int e=0;e<4;++e) accA[nt][e] = 0.f;

      #pragma unroll
      for (int k0 = 0; k0 < 32; k0 += 16) {
        u32 qh_[4], ql_[4];
        u32 ar = (u32)((rb*32 + mt*16 + lr)*TP + h*32 + k0 + lk*8)*2;
        ldmA(qh_, sm0+QH_OFF + ar);
        ldmA(ql_, sm0+QL_OFF + ar);
        #pragma unroll
        for (int nt = 0; nt < 8; ++nt){
          u32 kk[2];
          ldmB(kk, sm0+K_OFF + (u32)((nt*8 + br)*TP + h*32 + k0 + bk*8)*2);
          mma16816(accA[nt], qh_, kk);
          mma16816(accA[nt], ql_, kk);
        }
      }

      float o2a[4][4];
      #pragma unroll
      for (int nt=0;nt<4;++nt)
        #pragma unroll
        for (int e=0;e<4;++e) o2a[nt][e] = 0.f;

      const int r1 = rb*32 + mt*16 + quad, r2 = r1 + 8;
      #pragma unroll
      for (int sf = 0; sf < 4; ++sf) {
        int sA = sf*16 + 2*qc, sB = sA + 8;
        float v00 = fin(r1, sA,   accA[2*sf  ][0], h, bias_table, mrow);
        float v01 = fin(r1, sA+1, accA[2*sf  ][1], h, bias_table, mrow);
        float v10 = fin(r2, sA,   accA[2*sf  ][2], h, bias_table, mrow);
        float v11 = fin(r2, sA+1, accA[2*sf  ][3], h, bias_table, mrow);
        float w00 = fin(r1, sB,   accA[2*sf+1][0], h, bias_table, mrow);
        float w01 = fin(r1, sB+1, accA[2*sf+1][1], h, bias_table, mrow);
        float w10 = fin(r2, sB,   accA[2*sf+1][2], h, bias_table, mrow);
        float w11 = fin(r2, sB+1, accA[2*sf+1][3], h, bias_table, mrow);
        u32 ah_[4], al_[4];
        pksplit(v00, v01, ah_[0], al_[0]);   // P hi/lo: 2-term attn@v
        pksplit(v10, v11, ah_[1], al_[1]);
        pksplit(w00, w01, ah_[2], al_[2]);
        pksplit(w10, w11, ah_[3], al_[3]);
        #pragma unroll
        for (int nt2 = 0; nt2 < 4; ++nt2) {
          u32 vv[2];
          ldmBt(vv, sm0+X_OFF + (u32)((sf*16 + lr16)*TP + h*32 + nt2*8)*2);
          mma16816(o2a[nt2], ah_, vv);
          mma16816(o2a[nt2], al_, vv);
        }
      }
      // o2 slab -> q region (exactly the rows/cols this warp just consumed)
      #pragma unroll
      for (int nt2 = 0; nt2 < 4; ++nt2) {
        int c = h*32 + nt2*8 + 2*qc;
        split_store2(smc+QH_OFF, smc+QL_OFF, (u32)(r1*TP + c)*2,
                     o2a[nt2][0], o2a[nt2][1]);
        split_store2(smc+QH_OFF, smc+QL_OFF, (u32)(r2*TP + c)*2,
                     o2a[nt2][2], o2a[nt2][3]);
      }
    }
  }
  __syncthreads();

  // ---- stage 4: out = o2 @ proj_w^T + b (A hi/lo, 2-term) -----------------
  {
    float acc[2][4][4];
    #pragma unroll
    for (int mt=0;mt<2;++mt)
      #pragma unroll
      for (int nt=0;nt<4;++nt)
        #pragma unroll
        for (int e=0;e<4;++e) acc[mt][nt][e] = 0.f;

    mma_gemm_hl(sm0+QH_OFF, sm0+QL_OFF, sm0+W_OFF,
                wm, wn, lr, lk, br, bk, acc);
    __syncthreads();                  // o_s aliases Q: all A reads must drain

    float* o_s = reinterpret_cast<float*>(smc + OS_OFF);
    #pragma unroll
    for (int mt = 0; mt < 2; ++mt)
      #pragma unroll
      for (int nt = 0; nt < 4; ++nt) {
        int c  = wn*32 + nt*8 + qc*2;
        float2 bb = __ldg(reinterpret_cast<const float2*>(proj_b + c));
        int r1 = wm*32 + mt*16 + quad, r2 = r1 + 8;
        if (r1 < T49)
          *reinterpret_cast<float2*>(&o_s[r1*OP + c]) =
              make_float2(acc[mt][nt][0]+bb.x, acc[mt][nt][1]+bb.y);
        if (r2 < T49)
          *reinterpret_cast<float2*>(&o_s[r2*OP + c]) =
              make_float2(acc[mt][nt][2]+bb.x, acc[mt][nt][3]+bb.y);
      }
  }
  __syncthreads();

  // ---- coalesced store ----------------------------------------------------
  {
    const float* o_s = reinterpret_cast<const float*>(smc + OS_OFF);
    float4* og = reinterpret_cast<float4*>(out + (size_t)b*(T49*CDIM));
    #pragma unroll
    for (int it = 0; it < 7; ++it) {
      int e4 = tid + it*256;
      if (e4 < T49*32) {
        int r = e4 >> 5, c4 = (e4 & 31)*4;
        og[e4] = *reinterpret_cast<const float4*>(&o_s[r*OP + c4]);
      }
    }
  }
}

extern "C" void kernel_launch(void* const* d_in, const int* in_sizes, int n_in,
                              void* d_out, int out_size)
{
  const float* x      = (const float*)d_in[0];
  const float* mask   = (const float*)d_in[1];
  const float* qkv_w  = (const float*)d_in[2];
  const float* qkv_b  = (const float*)d_in[3];
  const float* proj_w = (const float*)d_in[4];
  const float* proj_b = (const float*)d_in[5];
  const float* btab   = (const float*)d_in[6];
  float* out = (float*)d_out;

  int B = in_sizes[0] / (T49*CDIM);   // 8192 windows

  cudaFuncSetAttribute(wattn_kernel,
                       cudaFuncAttributeMaxDynamicSharedMemorySize, SMEM_BYTES);
  wattn_kernel<<<B, 256, SMEM_BYTES>>>(x, mask, qkv_w, qkv_b,
                                       proj_w, proj_b, btab, out);
}

// round 17
// speedup vs baseline: 4.7899x; 1.1812x over previous
#include <cuda_runtime.h>
#include <cuda_fp16.h>

typedef unsigned long long u64;
typedef unsigned int u32;

#define T49   49
#define CDIM  128
#define NH    4
#define TP    136      /* fp16 tile pitch in elements (272B/row) */
#define OP    132      /* o_s fp32 pitch */

/* byte offsets (all fp16 tiles are 64x136 = 17408B unless noted) */
#define X_OFF   0                  /* x single fp16 ; v single alias      */
#define QH_OFF  17408              /* q hi -> o2 hi (in-place, slab-wise) */
#define QL_OFF  34816              /* q lo -> o2 lo                       */
#define K_OFF   52224              /* k single fp16                       */
#define W_OFF   69632              /* W single fp16, 128x136 = 34816      */
#define OS_OFF  17408              /* o_s fp32 aliases QH/QL after proj   */
#define SMEM_BYTES 104448          /* 2 CTAs/SM                           */

/* precomputed tables (written by prep kernel each launch) */
__device__ __half g_w16[65536];          /* qkv_w (49152) + proj_w (16384)    */
__device__ __half g_bm[64*4*64*56];      /* bias+mask, zero-padded, 1.75MB    */

// ---------------- helpers --------------------------------------------------
__device__ __forceinline__ u32 smem_u32(const void* p){
  u32 a; asm("{ .reg .u64 t; cvta.to.shared.u64 t, %1; cvt.u32.u64 %0, t; }"
             : "=r"(a) : "l"(p));
  return a;
}
__device__ __forceinline__ u32 pkh(float lo, float hi){   // low half = lo
  u32 r; asm("cvt.rn.f16x2.f32 %0, %1, %2;" : "=r"(r) : "f"(hi), "f"(lo));
  return r;
}
__device__ __forceinline__ void pksplit(float a, float b, u32 &hw, u32 &lw){
  __half ha=__float2half_rn(a), hb=__float2half_rn(b);
  hw = (u32)__half_as_ushort(ha) | ((u32)__half_as_ushort(hb)<<16);
  lw = (u32)__half_as_ushort(__float2half_rn(a-__half2float(ha)))
     | ((u32)__half_as_ushort(__float2half_rn(b-__half2float(hb)))<<16);
}
__device__ __forceinline__ void split_store2(char* th_, char* tl_, u32 off,
                                             float a, float b){
  u32 hw, lw; pksplit(a, b, hw, lw);
  *reinterpret_cast<u32*>(th_+off) = hw;
  *reinterpret_cast<u32*>(tl_+off) = lw;
}
// stage a 128x128 fp16 weight block (pre-converted): pure 16B copy
__device__ __forceinline__ void stage_w16(char* dw, const __half* wg, int tid){
  #pragma unroll
  for (int it = 0; it < 8; ++it){
    int e8 = tid + it*256;                 // 2048 groups of 8 halfs
    int n = e8 >> 4, k8 = (e8 & 15)*8;
    float4 v = __ldg(reinterpret_cast<const float4*>(wg + n*CDIM + k8));
    *reinterpret_cast<float4*>(dw + (u32)(n*TP + k8)*2) = v;
  }
}
// ---------------- mma.sync / ldmatrix --------------------------------------
__device__ __forceinline__ void ldmA(u32* r, u32 addr){
  asm volatile("ldmatrix.sync.aligned.m8n8.x4.shared.b16 {%0,%1,%2,%3}, [%4];"
    : "=r"(r[0]),"=r"(r[1]),"=r"(r[2]),"=r"(r[3]) : "r"(addr));
}
__device__ __forceinline__ void ldmB(u32* r, u32 addr){
  asm volatile("ldmatrix.sync.aligned.m8n8.x2.shared.b16 {%0,%1}, [%2];"
    : "=r"(r[0]),"=r"(r[1]) : "r"(addr));
}
__device__ __forceinline__ void ldmBt(u32* r, u32 addr){
  asm volatile("ldmatrix.sync.aligned.m8n8.x2.trans.shared.b16 {%0,%1}, [%2];"
    : "=r"(r[0]),"=r"(r[1]) : "r"(addr));
}
__device__ __forceinline__ void mma16816(float* c, const u32* a, const u32* b){
  asm volatile("mma.sync.aligned.m16n8k16.row.col.f32.f16.f16.f32 "
    "{%0,%1,%2,%3}, {%4,%5,%6,%7}, {%8,%9}, {%0,%1,%2,%3};"
    : "+f"(c[0]),"+f"(c[1]),"+f"(c[2]),"+f"(c[3])
    : "r"(a[0]),"r"(a[1]),"r"(a[2]),"r"(a[3]), "r"(b[0]),"r"(b[1]));
}
// 64x128x128 GEMM, A single, B single (1 term); warp tile 32x32, grid 2x4
__device__ __forceinline__ void mma_gemm_ss(
    u32 aS, u32 bS, int wm, int wn, int lr, int lk, int br, int bk,
    float acc[2][4][4])
{
  #pragma unroll
  for (int k0 = 0; k0 < 128; k0 += 16){
    u32 a_[2][4], b_[4][2];
    #pragma unroll
    for (int mt = 0; mt < 2; ++mt)
      ldmA(a_[mt], aS + (u32)((wm*32 + mt*16 + lr)*TP + k0 + lk*8)*2);
    #pragma unroll
    for (int nt = 0; nt < 4; ++nt)
      ldmB(b_[nt], bS + (u32)((wn*32 + nt*8 + br)*TP + k0 + bk*8)*2);
    #pragma unroll
    for (int mt = 0; mt < 2; ++mt)
      #pragma unroll
      for (int nt = 0; nt < 4; ++nt)
        mma16816(acc[mt][nt], a_[mt], b_[nt]);
  }
}
// A hi/lo, B single (2 terms) — proj
__device__ __forceinline__ void mma_gemm_hl(
    u32 aH, u32 aL, u32 bS, int wm, int wn, int lr, int lk, int br, int bk,
    float acc[2][4][4])
{
  #pragma unroll
  for (int k0 = 0; k0 < 128; k0 += 16){
    u32 ah[2][4], al[2][4], b_[4][2];
    #pragma unroll
    for (int mt = 0; mt < 2; ++mt){
      u32 ar = (u32)((wm*32 + mt*16 + lr)*TP + k0 + lk*8)*2;
      ldmA(ah[mt], aH + ar);
      ldmA(al[mt], aL + ar);
    }
    #pragma unroll
    for (int nt = 0; nt < 4; ++nt)
      ldmB(b_[nt], bS + (u32)((wn*32 + nt*8 + br)*TP + k0 + bk*8)*2);
    #pragma unroll
    for (int mt = 0; mt < 2; ++mt)
      #pragma unroll
      for (int nt = 0; nt < 4; ++nt){
        mma16816(acc[mt][nt], ah[mt], b_[nt]);
        mma16816(acc[mt][nt], al[mt], b_[nt]);
      }
  }
}

// ---------------- prep kernel: fp16 weights + padded bias/mask table -------
__global__ void __launch_bounds__(256)
wattn_prep(const float* __restrict__ qkv_w, const float* __restrict__ proj_w,
           const float* __restrict__ mask, const float* __restrict__ bias_table)
{
  u32 i0 = blockIdx.x*256 + threadIdx.x;          // 262144 threads
  if (i0 < 49152)      g_w16[i0] = __float2half_rn(__ldg(&qkv_w[i0]));
  else if (i0 < 65536) g_w16[i0] = __float2half_rn(__ldg(&proj_w[i0-49152]));
  // g_bm[((win*4 + h)*64 + t)*56 + s]; zero outside 49x49
  for (u32 j = i0; j < 64u*4*64*56; j += 262144u) {
    int s = j % 56; u32 r = j / 56;
    int t = r & 63; u32 hw_ = r >> 6;
    int h = hw_ & 3; u32 win = hw_ >> 2;
    float v = 0.f;
    if (t < T49 && s < T49) {
      int th=t/7, tw=t-th*7, sh=s/7, sw=s-sh*7;
      int rel=(th-sh+6)*13+(tw-sw+6);
      v = __ldg(&bias_table[rel*NH+h]) + __ldg(&mask[win*2401u + t*T49 + s]);
    }
    g_bm[j] = __float2half_rn(v);
  }
}

__global__ void __launch_bounds__(256, 2)
wattn_kernel(const float* __restrict__ x, const float* __restrict__ qkv_b,
             const float* __restrict__ proj_b, float* __restrict__ out)
{
  extern __shared__ char smc[];
  const u32 sm0 = smem_u32(smc);

  const int b   = blockIdx.x;
  const int tid = threadIdx.x;
  const int tx  = tid & 31;
  const int w   = tid >> 5;                 // warp 0..7
  const int lr = tx & 15, lk = tx >> 4;     // A ldmatrix roles
  const int br = tx & 7,  bk = (tx >> 3) & 1;
  const int quad = tx >> 2, qc = tx & 3;    // D fragment roles
  const int wm = w & 1, wn = w >> 1;        // GEMM warp grid 2x4, tile 32x32

  // ---- stage 1: x (single fp16); Wqkv ch0 ---------------------------------
  {
    const float4* xg = reinterpret_cast<const float4*>(x + (size_t)b*(T49*CDIM));
    #pragma unroll
    for (int it = 0; it < 7; ++it) {
      int e4 = tid + it*256;
      if (e4 < T49*32) {
        int r = e4 >> 5, c4 = (e4 & 31)*4;
        float4 v = __ldg(xg + e4);
        *reinterpret_cast<u64*>(smc + X_OFF + (u32)(r*TP + c4)*2) =
            (u64)pkh(v.x, v.y) | ((u64)pkh(v.z, v.w)<<32);
      }
    }
    stage_w16(smc+W_OFF, g_w16, tid);
  }
  __syncthreads();

  // ---- stage 2: QKV GEMM (1-term), epilogue -> q hi/lo, k single, v single
  const float scale = 0.17677669529663687f;     // 32^-0.5 (folded into q)
  #pragma unroll 1
  for (int ch = 0; ch < 3; ++ch) {
    float acc[2][4][4];
    #pragma unroll
    for (int mt=0;mt<2;++mt)
      #pragma unroll
      for (int nt=0;nt<4;++nt)
        #pragma unroll
        for (int e=0;e<4;++e) acc[mt][nt][e] = 0.f;

    mma_gemm_ss(sm0+X_OFF, sm0+W_OFF, wm, wn, lr, lk, br, bk, acc);
    if (ch == 2) __syncthreads();     // v overwrites x: all A reads must drain

    #pragma unroll
    for (int mt = 0; mt < 2; ++mt)
      #pragma unroll
      for (int nt = 0; nt < 4; ++nt) {
        int c  = wn*32 + nt*8 + qc*2;
        float2 bb = __ldg(reinterpret_cast<const float2*>(qkv_b + ch*CDIM + c));
        int r1 = wm*32 + mt*16 + quad, r2 = r1 + 8;
        float v0 = (r1 < T49) ? acc[mt][nt][0] + bb.x : 0.f;
        float v1 = (r1 < T49) ? acc[mt][nt][1] + bb.y : 0.f;
        float v2 = (r2 < T49) ? acc[mt][nt][2] + bb.x : 0.f;
        float v3 = (r2 < T49) ? acc[mt][nt][3] + bb.y : 0.f;
        if (ch == 0) {                       // q: hi/lo split, scaled
          split_store2(smc+QH_OFF, smc+QL_OFF, (u32)(r1*TP + c)*2,
                       v0*scale, v1*scale);
          split_store2(smc+QH_OFF, smc+QL_OFF, (u32)(r2*TP + c)*2,
                       v2*scale, v3*scale);
        } else {                             // k / v: single fp16
          char* dst = smc + ((ch==1) ? K_OFF : X_OFF);
          *reinterpret_cast<u32*>(dst + (u32)(r1*TP + c)*2) = pkh(v0, v1);
          *reinterpret_cast<u32*>(dst + (u32)(r2*TP + c)*2) = pkh(v2, v3);
        }
      }
    __syncthreads();
    if (ch < 2) {
      stage_w16(smc+W_OFF, g_w16 + (ch+1)*CDIM*CDIM, tid);
      __syncthreads();
    }
  }

  // ---- stage proj weights (W region dead; attention doesn't touch W) ------
  stage_w16(smc+W_OFF, g_w16 + 49152, tid);

  // ---- fused attention: slab-wise; bm table replaces bias/mask gathers ----
  {
    const int h = w >> 1, rb = w & 1;       // 4 heads x 2 row-blocks of 32
    const int lr16 = tx & 15;
    const __half* bmg = g_bm + (((u32)(b & 63)*NH + h) << 6)*56;  // [t][s] p56

    #pragma unroll 1
    for (int mt = 0; mt < 2; ++mt) {
      float accA[8][4];
      #pragma unroll
      for (int nt=0;nt<8;++nt)
        #pragma unroll
        for (int e=0;e<4;++e) accA[nt][e] = 0.f;

      #pragma unroll
      for (int k0 = 0; k0 < 32; k0 += 16) {
        u32 qh_[4], ql_[4];
        u32 ar = (u32)((rb*32 + mt*16 + lr)*TP + h*32 + k0 + lk*8)*2;
        ldmA(qh_, sm0+QH_OFF + ar);
        ldmA(ql_, sm0+QL_OFF + ar);
        #pragma unroll
        for (int nt = 0; nt < 8; ++nt){
          u32 kk[2];
          ldmB(kk, sm0+K_OFF + (u32)((nt*8 + br)*TP + h*32 + k0 + bk*8)*2);
          mma16816(accA[nt], qh_, kk);
          mma16816(accA[nt], ql_, kk);
        }
      }

      float o2a[4][4];
      #pragma unroll
      for (int nt=0;nt<4;++nt)
        #pragma unroll
        for (int e=0;e<4;++e) o2a[nt][e] = 0.f;

      const int r1 = rb*32 + mt*16 + quad, r2 = r1 + 8;
      #pragma unroll
      for (int sf = 0; sf < 4; ++sf) {
        int sA = sf*16 + 2*qc, sB = sA + 8;
        float2 f0 = __half22float2(__ldg(
            reinterpret_cast<const __half2*>(bmg + r1*56 + sA)));
        float2 f1 = __half22float2(__ldg(
            reinterpret_cast<const __half2*>(bmg + r2*56 + sA)));
        float2 f2 = __half22float2(__ldg(
            reinterpret_cast<const __half2*>(bmg + r1*56 + sB)));
        float2 f3 = __half22float2(__ldg(
            reinterpret_cast<const __half2*>(bmg + r2*56 + sB)));
        float v00 = accA[2*sf  ][0] + f0.x, v01 = accA[2*sf  ][1] + f0.y;
        float v10 = accA[2*sf  ][2] + f1.x, v11 = accA[2*sf  ][3] + f1.y;
        float w00 = accA[2*sf+1][0] + f2.x, w01 = accA[2*sf+1][1] + f2.y;
        float w10 = accA[2*sf+1][2] + f3.x, w11 = accA[2*sf+1][3] + f3.y;
        u32 ah_[4], al_[4];
        pksplit(v00, v01, ah_[0], al_[0]);   // P hi/lo: 2-term attn@v
        pksplit(v10, v11, ah_[1], al_[1]);
        pksplit(w00, w01, ah_[2], al_[2]);
        pksplit(w10, w11, ah_[3], al_[3]);
        #pragma unroll
        for (int nt2 = 0; nt2 < 4; ++nt2) {
          u32 vv[2];
          ldmBt(vv, sm0+X_OFF + (u32)((sf*16 + lr16)*TP + h*32 + nt2*8)*2);
          mma16816(o2a[nt2], ah_, vv);
          mma16816(o2a[nt2], al_, vv);
        }
      }
      // o2 slab -> q region (exactly the rows/cols this warp just consumed)
      #pragma unroll
      for (int nt2 = 0; nt2 < 4; ++nt2) {
        int c = h*32 + nt2*8 + 2*qc;
        split_store2(smc+QH_OFF, smc+QL_OFF, (u32)(r1*TP + c)*2,
                     o2a[nt2][0], o2a[nt2][1]);
        split_store2(smc+QH_OFF, smc+QL_OFF, (u32)(r2*TP + c)*2,
                     o2a[nt2][2], o2a[nt2][3]);
      }
    }
  }
  __syncthreads();

  // ---- stage 4: out = o2 @ proj_w^T + b (A hi/lo, 2-term) -----------------
  {
    float acc[2][4][4];
    #pragma unroll
    for (int mt=0;mt<2;++mt)
      #pragma unroll
      for (int nt=0;nt<4;++nt)
        #pragma unroll
        for (int e=0;e<4;++e) acc[mt][nt][e] = 0.f;

    mma_gemm_hl(sm0+QH_OFF, sm0+QL_OFF, sm0+W_OFF,
                wm, wn, lr, lk, br, bk, acc);
    __syncthreads();                  // o_s aliases Q: all A reads must drain

    float* o_s = reinterpret_cast<float*>(smc + OS_OFF);
    #pragma unroll
    for (int mt = 0; mt < 2; ++mt)
      #pragma unroll
      for (int nt = 0; nt < 4; ++nt) {
        int c  = wn*32 + nt*8 + qc*2;
        float2 bb = __ldg(reinterpret_cast<const float2*>(proj_b + c));
        int r1 = wm*32 + mt*16 + quad, r2 = r1 + 8;
        if (r1 < T49)
          *reinterpret_cast<float2*>(&o_s[r1*OP + c]) =
              make_float2(acc[mt][nt][0]+bb.x, acc[mt][nt][1]+bb.y);
        if (r2 < T49)
          *reinterpret_cast<float2*>(&o_s[r2*OP + c]) =
              make_float2(acc[mt][nt][2]+bb.x, acc[mt][nt][3]+bb.y);
      }
  }
  __syncthreads();

  // ---- coalesced store ----------------------------------------------------
  {
    const float* o_s = reinterpret_cast<const float*>(smc + OS_OFF);
    float4* og = reinterpret_cast<float4*>(out + (size_t)b*(T49*CDIM));
    #pragma unroll
    for (int it = 0; it < 7; ++it) {
      int e4 = tid + it*256;
      if (e4 < T49*32) {
        int r = e4 >> 5, c4 = (e4 & 31)*4;
        og[e4] = *reinterpret_cast<const float4*>(&o_s[r*OP + c4]);
      }
    }
  }
}

extern "C" void kernel_launch(void* const* d_in, const int* in_sizes, int n_in,
                              void* d_out, int out_size)
{
  const float* x      = (const float*)d_in[0];
  const float* mask   = (const float*)d_in[1];
  const float* qkv_w  = (const float*)d_in[2];
  const float* qkv_b  = (const float*)d_in[3];
  const float* proj_w = (const float*)d_in[4];
  const float* proj_b = (const float*)d_in[5];
  const float* btab   = (const float*)d_in[6];
  float* out = (float*)d_out;

  int B = in_sizes[0] / (T49*CDIM);   // 8192 windows

  wattn_prep<<<1024, 256>>>(qkv_w, proj_w, mask, btab);

  cudaFuncSetAttribute(wattn_kernel,
                       cudaFuncAttributeMaxDynamicSharedMemorySize, SMEM_BYTES);
  wattn_kernel<<<B, 256, SMEM_BYTES>>>(x, qkv_b, proj_b, out);
}